// round 12
// baseline (speedup 1.0000x reference)
#include <cuda_runtime.h>
#include <cstdint>

#define N_NODES 20000
#define N_EDGES 256000
#define DIM 128
#define DD (DIM*DIM)

#define RS2 20                      // HMMA smem row stride (u32): 16 data + 4 pad
#define IMG_U32 16384               // per-matrix bf16 image: 8192 hi + 8192 lo (u32)
#define UNION_U32 10240             // 40KB smem union

// ---------------- static device scratch ----------------
__device__ float  g_h   [N_NODES * DIM];
__device__ float  g_e   [N_EDGES * DIM];
__device__ float  g_abde[N_NODES * 4 * DIM];   // [node][ A | B | D | E ]
__device__ float  g_enew[N_EDGES * DIM];
__device__ float  g_hnew[N_NODES * DIM];
__device__ double g_stats[4 * DIM];
__device__ float  g_bn  [4 * DIM];
__device__ int    g_cnt [N_NODES];
__device__ int    g_cnt2[N_NODES];
__device__ int    g_csr [N_NODES + 1];
__device__ int    g_perm[N_EDGES];
__device__ int    g_srcp[N_EDGES];
__device__ uint32_t g_wimg[22 * IMG_U32];
__device__ int    g_hmma_ok;

// ---------------- bf16 helpers ----------------
__device__ __forceinline__ uint32_t pack2(float a, float b) {
    uint32_t r; asm("cvt.rn.bf16x2.f32 %0, %1, %2;" : "=r"(r) : "f"(b), "f"(a)); return r; // lo=a hi=b
}
__device__ __forceinline__ void split2(float a, float b, uint32_t& hi, uint32_t& lo) {
    hi = pack2(a, b);
    float ha = __uint_as_float(hi << 16);
    float hb = __uint_as_float(hi & 0xffff0000u);
    lo = pack2(a - ha, b - hb);
}
__device__ __forceinline__ void mma16816(float (&d)[4], const uint32_t (&a)[4],
                                         const uint32_t b0, const uint32_t b1) {
    asm volatile("mma.sync.aligned.m16n8k16.row.col.f32.bf16.bf16.f32 "
        "{%0,%1,%2,%3}, {%4,%5,%6,%7}, {%8,%9}, {%0,%1,%2,%3};"
        : "+f"(d[0]), "+f"(d[1]), "+f"(d[2]), "+f"(d[3])
        : "r"(a[0]), "r"(a[1]), "r"(a[2]), "r"(a[3]), "r"(b0), "r"(b1));
}
__device__ __forceinline__ void ldsm_x4(uint32_t (&r)[4], uint32_t saddr) {
    asm volatile("ldmatrix.sync.aligned.m8n8.x4.shared.b16 {%0,%1,%2,%3}, [%4];"
        : "=r"(r[0]), "=r"(r[1]), "=r"(r[2]), "=r"(r[3]) : "r"(saddr));
}

// ================= numeric HMMA probe =================
__global__ void k_probe() {
    uint32_t one2 = 0x3f803f80u;
    uint32_t a[4] = {one2, one2, one2, one2};
    float d[4] = {0.f, 0.f, 0.f, 0.f};
    mma16816(d, a, one2, one2);
    bool ok = (d[0] == 16.f) && (d[1] == 16.f) && (d[2] == 16.f) && (d[3] == 16.f);
    unsigned m = __ballot_sync(0xffffffffu, ok);
    if ((threadIdx.x & 31) == 0) g_hmma_ok = (m == 0xffffffffu) ? 1 : 0;
}

// ---------------- weight prep ----------------
__global__ void k_prep_w(const float* Wh, const float* We,
                         const float* Aw, const float* Bw, const float* Cw,
                         const float* Dw, const float* Ew)
{
    int bx = blockIdx.x;
    const float* W;
    if (bx == 0) W = Wh;
    else if (bx == 1) W = We;
    else {
        int i = bx - 2, l = i / 5, w = i % 5;
        W = ((w == 0) ? Aw : (w == 1) ? Bw : (w == 2) ? Cw : (w == 3) ? Dw : Ew) + (size_t)l * DD;
    }
    uint32_t* img = &g_wimg[(size_t)bx * IMG_U32];
    for (int p = threadIdx.x; p < 8192; p += blockDim.x) {
        int n = p >> 6, kp = p & 63, k = kp << 1;
        uint32_t hi, lo;
        split2(W[k * DIM + n], W[(k + 1) * DIM + n], hi, lo);
        img[n * 64 + kp] = hi;
        img[8192 + n * 64 + kp] = lo;
    }
}

// ================= SIMT fp32 mainloop (fallback) =================
__device__ __forceinline__ void gemm_mainloop(
    const float* __restrict__ A, const float* __restrict__ B,
    int M, int row0, float (&acc)[8][8],
    float (*As)[16][DIM], float (*Bs)[16][DIM])
{
    const int tid = threadIdx.x;
    const int ty = tid >> 4, tx = tid & 15;
    const int ar0 = tid >> 2, ac0 = (tid & 3) << 2;
    const int ar1 = ar0 + 64;
    const int br0 = tid >> 5, bc0 = (tid & 31) << 2;
    const int br1 = br0 + 8;
    const int r0 = row0 + ar0, r1 = row0 + ar1;
    const float4 z4 = make_float4(0.f, 0.f, 0.f, 0.f);
    float4 av0, av1, bv0, bv1;

    av0 = (r0 < M) ? *(const float4*)&A[(size_t)r0 * DIM + ac0] : z4;
    av1 = (r1 < M) ? *(const float4*)&A[(size_t)r1 * DIM + ac0] : z4;
    bv0 = *(const float4*)&B[br0 * DIM + bc0];
    bv1 = *(const float4*)&B[br1 * DIM + bc0];
    As[0][ac0+0][ar0] = av0.x; As[0][ac0+1][ar0] = av0.y; As[0][ac0+2][ar0] = av0.z; As[0][ac0+3][ar0] = av0.w;
    As[0][ac0+0][ar1] = av1.x; As[0][ac0+1][ar1] = av1.y; As[0][ac0+2][ar1] = av1.z; As[0][ac0+3][ar1] = av1.w;
    *(float4*)&Bs[0][br0][bc0] = bv0;
    *(float4*)&Bs[0][br1][bc0] = bv1;
    __syncthreads();

    av0 = (r0 < M) ? *(const float4*)&A[(size_t)r0 * DIM + 16 + ac0] : z4;
    av1 = (r1 < M) ? *(const float4*)&A[(size_t)r1 * DIM + 16 + ac0] : z4;
    bv0 = *(const float4*)&B[(16 + br0) * DIM + bc0];
    bv1 = *(const float4*)&B[(16 + br1) * DIM + bc0];

    #pragma unroll 1
    for (int it = 0; it < 8; it++) {
        const int cur = it & 1;
        #pragma unroll
        for (int k = 0; k < 16; k++) {
            float a[8], b[8];
            *(float4*)(a)   = *(const float4*)&As[cur][k][ty*8];
            *(float4*)(a+4) = *(const float4*)&As[cur][k][ty*8+4];
            *(float4*)(b)   = *(const float4*)&Bs[cur][k][tx*8];
            *(float4*)(b+4) = *(const float4*)&Bs[cur][k][tx*8+4];
            #pragma unroll
            for (int i = 0; i < 8; i++)
                #pragma unroll
                for (int j = 0; j < 8; j++)
                    acc[i][j] = fmaf(a[i], b[j], acc[i][j]);
        }
        if (it < 7) {
            const int nxt = cur ^ 1;
            As[nxt][ac0+0][ar0] = av0.x; As[nxt][ac0+1][ar0] = av0.y; As[nxt][ac0+2][ar0] = av0.z; As[nxt][ac0+3][ar0] = av0.w;
            As[nxt][ac0+0][ar1] = av1.x; As[nxt][ac0+1][ar1] = av1.y; As[nxt][ac0+2][ar1] = av1.z; As[nxt][ac0+3][ar1] = av1.w;
            *(float4*)&Bs[nxt][br0][bc0] = bv0;
            *(float4*)&Bs[nxt][br1][bc0] = bv1;
            __syncthreads();
            if (it < 6) {
                int kk = (it + 2) * 16;
                av0 = (r0 < M) ? *(const float4*)&A[(size_t)r0 * DIM + kk + ac0] : z4;
                av1 = (r1 < M) ? *(const float4*)&A[(size_t)r1 * DIM + kk + ac0] : z4;
                bv0 = *(const float4*)&B[(kk + br0) * DIM + bc0];
                bv1 = *(const float4*)&B[(kk + br1) * DIM + bc0];
            }
        }
    }
}

// ================= HMMA bf16x3 tile (K-tiled BK=32, ldmatrix fragments) =================
__device__ __forceinline__ void gemm_tile_hmma(
    const float* __restrict__ Asrc, int M, int row0, const uint32_t* __restrict__ wimg,
    uint32_t (*smA)[128 * RS2], uint32_t (*smB)[128 * RS2],
    float (&acc)[2][8][4])
{
    int tid = threadIdx.x, lid = tid & 31, wid = tid >> 5;
    int wm = wid & 3, wn = wid >> 2;
    int lrow = lid & 7, lj = lid >> 3;
    int a_row_off = ((lj & 1) << 3) + lrow;
    int a_word    = (lj >> 1) << 2;
    int b_row_off = ((lj >> 1) << 3) + lrow;
    int b_word    = (lj & 1) << 2;
    uint32_t sA0 = (uint32_t)__cvta_generic_to_shared(&smA[0][0]);
    uint32_t sA1 = (uint32_t)__cvta_generic_to_shared(&smA[1][0]);
    uint32_t sB0 = (uint32_t)__cvta_generic_to_shared(&smB[0][0]);
    uint32_t sB1 = (uint32_t)__cvta_generic_to_shared(&smB[1][0]);

    #pragma unroll 1
    for (int it = 0; it < 4; it++) {
        if (it) __syncthreads();
        #pragma unroll
        for (int q = 0; q < 8; q++) {
            int p = tid + q * 256;
            int row = p >> 4, kpl = p & 15;
            int r = row0 + row;
            float2 v = (r < M) ? *(const float2*)&Asrc[(size_t)r * DIM + it * 32 + kpl * 2]
                               : make_float2(0.f, 0.f);
            uint32_t hi, lo;
            split2(v.x, v.y, hi, lo);
            smA[0][row * RS2 + kpl] = hi;
            smA[1][row * RS2 + kpl] = lo;
        }
        #pragma unroll
        for (int q = 0; q < 8; q++) {
            int p = tid + q * 256;
            int n = p >> 4, kpl = p & 15;
            smB[0][n * RS2 + kpl] = wimg[n * 64 + it * 16 + kpl];
            smB[1][n * RS2 + kpl] = wimg[8192 + n * 64 + it * 16 + kpl];
        }
        __syncthreads();
        #pragma unroll
        for (int kk = 0; kk < 2; kk++) {
            uint32_t ah[2][4], al[2][4];
            #pragma unroll
            for (int mi = 0; mi < 2; mi++) {
                uint32_t off = (uint32_t)(((wm * 32 + mi * 16 + a_row_off) * RS2
                                           + kk * 8 + a_word) * 4);
                ldsm_x4(ah[mi], sA0 + off);
                ldsm_x4(al[mi], sA1 + off);
            }
            #pragma unroll
            for (int np = 0; np < 4; np++) {
                uint32_t off = (uint32_t)(((wn * 64 + np * 16 + b_row_off) * RS2
                                           + kk * 8 + b_word) * 4);
                uint32_t bh[4], bl[4];
                ldsm_x4(bh, sB0 + off);
                ldsm_x4(bl, sB1 + off);
                #pragma unroll
                for (int s = 0; s < 2; s++) {
                    int ni = np * 2 + s;
                    #pragma unroll
                    for (int mi = 0; mi < 2; mi++) {
                        mma16816(acc[mi][ni], ah[mi], bh[s*2], bh[s*2+1]);
                        mma16816(acc[mi][ni], ah[mi], bl[s*2], bl[s*2+1]);
                        mma16816(acc[mi][ni], al[mi], bh[s*2], bh[s*2+1]);
                    }
                }
            }
        }
    }
}

// fp32 output store for HMMA layout
__device__ __forceinline__ void hmma_store(
    float (&acc)[2][8][4], int M, int row0, float* __restrict__ out, int ldc, int cbase,
    const float* __restrict__ s_bias)
{
    int tid = threadIdx.x, lid = tid & 31, wid = tid >> 5;
    int g = lid >> 2, t = lid & 3;
    int wm = wid & 3, wn = wid >> 2;
    #pragma unroll
    for (int mi = 0; mi < 2; mi++)
        #pragma unroll
        for (int hf = 0; hf < 2; hf++) {
            int r = row0 + wm * 32 + mi * 16 + hf * 8 + g;
            if (r < M) {
                #pragma unroll
                for (int ni = 0; ni < 8; ni++) {
                    int c = wn * 64 + ni * 8 + t * 2;
                    *(float2*)&out[(size_t)r * ldc + cbase + c] = make_float2(
                        acc[mi][ni][hf * 2 + 0] + s_bias[c],
                        acc[mi][ni][hf * 2 + 1] + s_bias[c + 1]);
                }
            }
        }
}

// ---------------- unified GEMM (embeddings) ----------------
__global__ void __launch_bounds__(256, 2) k_gemm_plain(
    const float* __restrict__ A, const float* __restrict__ W, int widx,
    const float* __restrict__ bias, int M, int which)
{
    __shared__ __align__(16) uint32_t smraw[UNION_U32];
    __shared__ float s_bias[DIM];
    int tid = threadIdx.x;
    int row0 = blockIdx.x * 128;
    float* out = which ? g_e : g_h;
    if (tid < DIM) s_bias[tid] = bias[tid];
    __syncthreads();

    if (g_hmma_ok) {
        uint32_t (*hA)[128 * RS2] = reinterpret_cast<uint32_t(*)[128 * RS2]>(smraw);
        uint32_t (*hB)[128 * RS2] = reinterpret_cast<uint32_t(*)[128 * RS2]>(smraw + 2 * 128 * RS2);
        float acc[2][8][4] = {};
        gemm_tile_hmma(A, M, row0, &g_wimg[(size_t)widx * IMG_U32], hA, hB, acc);
        hmma_store(acc, M, row0, out, DIM, 0, s_bias);
    } else {
        float (*As)[16][DIM] = reinterpret_cast<float(*)[16][DIM]>(smraw);
        float (*Bs)[16][DIM] = reinterpret_cast<float(*)[16][DIM]>(smraw + 4096);
        float acc[8][8] = {};
        gemm_mainloop(A, W, M, row0, acc, As, Bs);
        int tx = tid & 15, ty = tid >> 4;
        int c0 = tx * 8;
        #pragma unroll
        for (int i = 0; i < 8; i++) {
            int r = row0 + ty*8 + i;
            if (r < M) {
                #pragma unroll
                for (int j = 0; j < 8; j++)
                    out[(size_t)r * DIM + c0 + j] = acc[i][j] + s_bias[c0 + j];
            }
        }
    }
}

// ---------------- unified node GEMM: grid.y selects A/B/D/E ----------------
__global__ void __launch_bounds__(256, 2) k_gemm_node(
    int l, const float* __restrict__ Aw, const float* __restrict__ Bw,
    const float* __restrict__ Dw, const float* __restrict__ Ew,
    const float* __restrict__ Ab, const float* __restrict__ Bb,
    const float* __restrict__ Db, const float* __restrict__ Eb)
{
    __shared__ __align__(16) uint32_t smraw[UNION_U32];
    __shared__ float s_bias[DIM];
    int tid = threadIdx.x;
    int row0 = blockIdx.x * 128;
    int y = blockIdx.y;
    int base = 2 + l * 5;
    int widx = (y == 0) ? base : (y == 1) ? base + 1 : (y == 2) ? base + 3 : base + 4;
    const float* W  = (y == 0) ? Aw : (y == 1) ? Bw : (y == 2) ? Dw : Ew;
    const float* bb = (y == 0) ? Ab : (y == 1) ? Bb : (y == 2) ? Db : Eb;
    if (tid < DIM) s_bias[tid] = bb[tid];
    __syncthreads();

    if (g_hmma_ok) {
        uint32_t (*hA)[128 * RS2] = reinterpret_cast<uint32_t(*)[128 * RS2]>(smraw);
        uint32_t (*hB)[128 * RS2] = reinterpret_cast<uint32_t(*)[128 * RS2]>(smraw + 2 * 128 * RS2);
        float acc[2][8][4] = {};
        gemm_tile_hmma(g_h, N_NODES, row0, &g_wimg[(size_t)widx * IMG_U32], hA, hB, acc);
        hmma_store(acc, N_NODES, row0, g_abde, 512, y * DIM, s_bias);
    } else {
        float (*As)[16][DIM] = reinterpret_cast<float(*)[16][DIM]>(smraw);
        float (*Bs)[16][DIM] = reinterpret_cast<float(*)[16][DIM]>(smraw + 4096);
        float acc[8][8] = {};
        gemm_mainloop(g_h, W, N_NODES, row0, acc, As, Bs);
        int tx = tid & 15, ty = tid >> 4;
        int c0 = tx * 8;
        #pragma unroll
        for (int i = 0; i < 8; i++) {
            int r = row0 + ty*8 + i;
            if (r < N_NODES) {
                #pragma unroll
                for (int j = 0; j < 8; j++)
                    g_abde[(size_t)r * 512 + y * DIM + c0 + j] = acc[i][j] + s_bias[c0 + j];
            }
        }
    }
}

// ---------------- unified edge GEMM + gather + (optional) e-BN stats ----------------
__global__ void __launch_bounds__(256, 2) k_gemm_edge(
    int l, const float* __restrict__ Cw, const float* __restrict__ Cb,
    const int* __restrict__ src, const int* __restrict__ dst, int do_estats)
{
    __shared__ __align__(16) uint32_t smraw[UNION_U32];
    __shared__ float s_cb[DIM], s_sum[DIM], s_sq[DIM];
    int tid = threadIdx.x, lid = tid & 31, wid = tid >> 5;
    int row0 = blockIdx.x * 128;
    if (tid < DIM) { s_cb[tid] = Cb[tid]; s_sum[tid] = 0.f; s_sq[tid] = 0.f; }
    __syncthreads();

    if (g_hmma_ok) {
        uint32_t (*hA)[128 * RS2] = reinterpret_cast<uint32_t(*)[128 * RS2]>(smraw);
        uint32_t (*hB)[128 * RS2] = reinterpret_cast<uint32_t(*)[128 * RS2]>(smraw + 2 * 128 * RS2);
        int g = lid >> 2, t = lid & 3;
        int wm = wid & 3, wn = wid >> 2;
        float acc[2][8][4] = {};
        gemm_tile_hmma(g_e, N_EDGES, row0, &g_wimg[(size_t)(2 + l * 5 + 2) * IMG_U32], hA, hB, acc);

        int rows[4], svr[4], dvr[4];
        #pragma unroll
        for (int ridx = 0; ridx < 4; ridx++) {
            int mi = ridx >> 1, hf = ridx & 1;
            rows[ridx] = row0 + wm * 32 + mi * 16 + hf * 8 + g;
            svr[ridx] = src[rows[ridx]];
            dvr[ridx] = dst[rows[ridx]];
        }
        #pragma unroll
        for (int ni = 0; ni < 8; ni++) {
            int c = wn * 64 + ni * 8 + t * 2;
            float cb0 = s_cb[c], cb1 = s_cb[c + 1];
            float s0 = 0.f, s1 = 0.f, q0 = 0.f, q1 = 0.f;
            #pragma unroll
            for (int ridx = 0; ridx < 4; ridx++) {
                int mi = ridx >> 1, hf = ridx & 1;
                float2 dD = *(const float2*)&g_abde[(size_t)svr[ridx] * 512 + 256 + c];
                float2 dE = *(const float2*)&g_abde[(size_t)dvr[ridx] * 512 + 384 + c];
                float v0 = acc[mi][ni][hf * 2 + 0] + cb0 + dD.x + dE.x;
                float v1 = acc[mi][ni][hf * 2 + 1] + cb1 + dD.y + dE.y;
                *(float2*)&g_enew[(size_t)rows[ridx] * DIM + c] = make_float2(v0, v1);
                s0 += v0; q0 += v0 * v0;
                s1 += v1; q1 += v1 * v1;
            }
            if (do_estats) {
                #pragma unroll
                for (int s = 4; s < 32; s <<= 1) {
                    s0 += __shfl_xor_sync(0xffffffffu, s0, s);
                    s1 += __shfl_xor_sync(0xffffffffu, s1, s);
                    q0 += __shfl_xor_sync(0xffffffffu, q0, s);
                    q1 += __shfl_xor_sync(0xffffffffu, q1, s);
                }
                if (g == 0) {
                    atomicAdd(&s_sum[c], s0);     atomicAdd(&s_sq[c], q0);
                    atomicAdd(&s_sum[c + 1], s1); atomicAdd(&s_sq[c + 1], q1);
                }
            }
        }
    } else {
        float (*As)[16][DIM] = reinterpret_cast<float(*)[16][DIM]>(smraw);
        float (*Bs)[16][DIM] = reinterpret_cast<float(*)[16][DIM]>(smraw + 4096);
        float acc[8][8] = {};
        gemm_mainloop(g_e, Cw, N_EDGES, row0, acc, As, Bs);
        __syncthreads();
        int tx = tid & 15, ty = tid >> 4;
        int c0 = tx * 8;
        float cb[8];
        #pragma unroll
        for (int j = 0; j < 8; j++) cb[j] = s_cb[c0 + j];
        float csum[8] = {}, csq[8] = {};
        #pragma unroll 1
        for (int i = 0; i < 8; i++) {
            int r = row0 + ty*8 + i;
            int sv = src[r], dv = dst[r];
            const float* Dp = &g_abde[(size_t)sv * 512 + 256 + c0];
            const float* Ep = &g_abde[(size_t)dv * 512 + 384 + c0];
            float dh[8], eh[8], ev[8];
            *(float4*)(dh)   = *(const float4*)(Dp);
            *(float4*)(dh+4) = *(const float4*)(Dp+4);
            *(float4*)(eh)   = *(const float4*)(Ep);
            *(float4*)(eh+4) = *(const float4*)(Ep+4);
            #pragma unroll
            for (int j = 0; j < 8; j++) {
                float v = acc[i][j] + cb[j] + dh[j] + eh[j];
                ev[j] = v;
                csum[j] += v;
                csq[j]  += v * v;
            }
            *(float4*)&g_enew[(size_t)r * DIM + c0]     = *(float4*)(ev);
            *(float4*)&g_enew[(size_t)r * DIM + c0 + 4] = *(float4*)(ev+4);
        }
        if (do_estats) {
            #pragma unroll
            for (int j = 0; j < 8; j++) {
                atomicAdd(&s_sum[c0 + j], csum[j]);
                atomicAdd(&s_sq[c0 + j],  csq[j]);
            }
        }
    }
    __syncthreads();
    if (do_estats && tid < DIM) {
        atomicAdd(&g_stats[2*DIM + tid], (double)s_sum[tid]);
        atomicAdd(&g_stats[3*DIM + tid], (double)s_sq[tid]);
    }
}

// ================= CSR build =================
__global__ void k_zero_cnt() {
    int i = blockIdx.x * blockDim.x + threadIdx.x;
    if (i < N_NODES) { g_cnt[i] = 0; g_cnt2[i] = 0; }
}
__global__ void k_hist(const int* __restrict__ dst) {
    int e = blockIdx.x * blockDim.x + threadIdx.x;
    if (e < N_EDGES) atomicAdd(&g_cnt[dst[e]], 1);
}
__global__ void k_scan() {
    __shared__ int s[1024];
    int tn = threadIdx.x;
    int base = tn * 20;
    int loc[20];
    int sum = 0;
    #pragma unroll
    for (int j = 0; j < 20; j++) {
        int idx = base + j;
        loc[j] = sum;
        if (idx < N_NODES) sum += g_cnt[idx];
    }
    s[tn] = sum;
    __syncthreads();
    for (int off = 1; off < 1024; off <<= 1) {
        int v = (tn >= off) ? s[tn - off] : 0;
        __syncthreads();
        s[tn] += v;
        __syncthreads();
    }
    int pre = (tn > 0) ? s[tn - 1] : 0;
    #pragma unroll
    for (int j = 0; j < 20; j++) {
        int idx = base + j;
        if (idx < N_NODES) g_csr[idx] = pre + loc[j];
    }
    if (tn == 1023) g_csr[N_NODES] = s[1023];
}
__global__ void k_scatter(const int* __restrict__ src, const int* __restrict__ dst) {
    int e = blockIdx.x * blockDim.x + threadIdx.x;
    if (e < N_EDGES) {
        int d = dst[e];
        int pos = g_csr[d] + atomicAdd(&g_cnt2[d], 1);
        g_perm[pos] = e;
        g_srcp[pos] = src[e];
    }
}
__global__ void k_zero_stats() {
    int i = threadIdx.x;
    if (i < 4 * DIM) g_stats[i] = 0.0;
}

// ---------------- per-node aggregation + fused apply_e ----------------
// For each edge of node n: v = enew[e][t]; sigma drives num/den; if apply:
// g_e[e][t] += relu(v*sc + sh)  (each edge row touched exactly once via perm)
__global__ void __launch_bounds__(128) k_aggregate(int apply) {
    int n = blockIdx.x;
    int t = threadIdx.x;
    int beg = g_csr[n], end = g_csr[n + 1];
    float sc = g_bn[2*DIM + t];
    float sh = g_bn[3*DIM + t];
    float num = 0.f, den = 0.f;
    for (int i = beg; i < end; i++) {
        int e = g_perm[i];
        int s = g_srcp[i];
        float v = g_enew[(size_t)e * DIM + t];
        float bh = g_abde[(size_t)s * 512 + 128 + t];
        float sg = 1.f / (1.f + __expf(-v));
        num = fmaf(sg, bh, num);
        den += sg;
        if (apply) {
            g_e[(size_t)e * DIM + t] += fmaxf(fmaf(v, sc, sh), 0.f);
        }
    }
    float hv = g_abde[(size_t)n * 512 + t] + num / (den + 1e-6f);
    g_hnew[n * DIM + t] = hv;
}

__global__ void __launch_bounds__(256) k_hstats() {
    __shared__ float s_sum[DIM];
    __shared__ float s_sq[DIM];
    int tid = threadIdx.x;
    if (tid < DIM) { s_sum[tid] = 0.f; s_sq[tid] = 0.f; }
    __syncthreads();
    int col = tid & 127;
    int rh = tid >> 7;
    int row0 = blockIdx.x * 128;
    float ls = 0.f, lq = 0.f;
    for (int i = rh; i < 128; i += 2) {
        int r = row0 + i;
        if (r < N_NODES) {
            float v = g_hnew[r * DIM + col];
            ls += v; lq += v * v;
        }
    }
    atomicAdd(&s_sum[col], ls);
    atomicAdd(&s_sq[col], lq);
    __syncthreads();
    if (tid < DIM) {
        atomicAdd(&g_stats[tid],       (double)s_sum[tid]);
        atomicAdd(&g_stats[DIM + tid], (double)s_sq[tid]);
    }
}

// e-BN params (stats complete after edge GEMM)
__global__ void k_finalize_e(const float* __restrict__ ge, const float* __restrict__ be) {
    int c = threadIdx.x;
    if (c < DIM) {
        double mu  = g_stats[2*DIM + c] / (double)N_EDGES;
        double var = g_stats[3*DIM + c] / (double)N_EDGES - mu * mu;
        double rstd = 1.0 / sqrt(var + 1e-5);
        float sc = ge[c] * (float)rstd;
        g_bn[2*DIM + c] = sc;
        g_bn[3*DIM + c] = be[c] - (float)mu * sc;
    }
}
// h-BN params (stats complete after k_hstats)
__global__ void k_finalize_h(const float* __restrict__ gh, const float* __restrict__ bh) {
    int t = threadIdx.x;
    if (t < DIM) {
        double mu  = g_stats[t] / (double)N_NODES;
        double var = g_stats[DIM + t] / (double)N_NODES - mu * mu;
        double rstd = 1.0 / sqrt(var + 1e-5);
        float sc = gh[t] * (float)rstd;
        g_bn[t] = sc;
        g_bn[DIM + t] = bh[t] - (float)mu * sc;
    }
}

__global__ void k_apply_h() {
    int i4 = blockIdx.x * blockDim.x + threadIdx.x;
    if (i4 < N_NODES * DIM / 4) {
        int c4 = (i4 & 31) * 4;
        float4 v  = *(const float4*)&g_hnew[i4 * 4];
        float4 sc = *(const float4*)&g_bn[c4];
        float4 sh = *(const float4*)&g_bn[DIM + c4];
        float4 hv = *(const float4*)&g_h[i4 * 4];
        hv.x += fmaxf(fmaf(v.x, sc.x, sh.x), 0.f);
        hv.y += fmaxf(fmaf(v.y, sc.y, sh.y), 0.f);
        hv.z += fmaxf(fmaf(v.z, sc.z, sh.z), 0.f);
        hv.w += fmaxf(fmaf(v.w, sc.w, sh.w), 0.f);
        *(float4*)&g_h[i4 * 4] = hv;
    }
}

// ---------------- host launch ----------------
extern "C" void kernel_launch(void* const* d_in, const int* in_sizes, int n_in,
                              void* d_out, int out_size)
{
    const float* h0  = (const float*)d_in[0];
    const float* e0  = (const float*)d_in[1];
    const int*   src = (const int*)  d_in[2];
    const int*   dst = (const int*)  d_in[3];
    const float* Wh  = (const float*)d_in[4];
    const float* bhe = (const float*)d_in[5];
    const float* We  = (const float*)d_in[6];
    const float* bee = (const float*)d_in[7];
    const float* Aw  = (const float*)d_in[8];
    const float* Ab  = (const float*)d_in[9];
    const float* Bw  = (const float*)d_in[10];
    const float* Bb  = (const float*)d_in[11];
    const float* Cw  = (const float*)d_in[12];
    const float* Cb  = (const float*)d_in[13];
    const float* Dw  = (const float*)d_in[14];
    const float* Db  = (const float*)d_in[15];
    const float* Ew  = (const float*)d_in[16];
    const float* Eb  = (const float*)d_in[17];
    const float* gh  = (const float*)d_in[18];
    const float* bh  = (const float*)d_in[19];
    const float* ge  = (const float*)d_in[20];
    const float* be  = (const float*)d_in[21];

    const int grid_node = (N_NODES + 127) / 128;   // 157
    const int grid_edge = N_EDGES / 128;           // 2000

    k_probe<<<1, 32>>>();
    k_prep_w<<<22, 256>>>(Wh, We, Aw, Bw, Cw, Dw, Ew);
    k_gemm_plain<<<grid_node, 256>>>(h0, Wh, 0, bhe, N_NODES, 0);
    k_gemm_plain<<<grid_edge, 256>>>(e0, We, 1, bee, N_EDGES, 1);

    k_zero_cnt<<<(N_NODES + 255) / 256, 256>>>();
    k_hist<<<(N_EDGES + 255) / 256, 256>>>(dst);
    k_scan<<<1, 1024>>>();
    k_scatter<<<(N_EDGES + 255) / 256, 256>>>(src, dst);

    for (int l = 0; l < 4; l++) {
        int do_e = (l < 3) ? 1 : 0;   // e_3 is dead: no stats, no finalize, no apply
        k_zero_stats<<<1, 512>>>();
        k_gemm_node<<<dim3(grid_node, 4), 256>>>(l,
            Aw + l*DD, Bw + l*DD, Dw + l*DD, Ew + l*DD,
            Ab + l*DIM, Bb + l*DIM, Db + l*DIM, Eb + l*DIM);
        k_gemm_edge<<<grid_edge, 256>>>(l, Cw + l*DD, Cb + l*DIM, src, dst, do_e);
        if (do_e)
            k_finalize_e<<<1, 128>>>(ge + l*DIM, be + l*DIM);
        k_aggregate<<<N_NODES, 128>>>(do_e);   // fused apply_e (prev g_bn state valid)
        k_hstats<<<grid_node, 256>>>();
        k_finalize_h<<<1, 128>>>(gh + l*DIM, bh + l*DIM);
        k_apply_h<<<(N_NODES * DIM / 4 + 255) / 256, 256>>>();
    }

    cudaMemcpyFromSymbolAsync(d_out, g_h, sizeof(float) * N_NODES * DIM, 0,
                              cudaMemcpyDeviceToDevice, 0);
}

// round 13
// speedup vs baseline: 1.0144x; 1.0144x over previous
#include <cuda_runtime.h>
#include <cstdint>

#define N_NODES 20000
#define N_EDGES 256000
#define DIM 128
#define DD (DIM*DIM)

#define RS2 20                       // B-slice smem row stride (u32)
#define RSA 68                       // full-K A smem row stride (u32), ldsm conflict-free
#define IMG_U32 16384                // per-matrix bf16 image (8192 hi + 8192 lo)
#define A_SPLIT_OFF (128 * RSA)      // 8704 u32
#define B_BASE      (2 * 128 * RSA)  // 17408 u32
#define B_SPLIT_OFF (128 * RS2)      // 2560 u32
#define DYN_U32   (B_BASE + 2 * B_SPLIT_OFF)   // 22528 u32
#define DYN_BYTES (DYN_U32 * 4)                // 90112 B

// ---------------- static device scratch ----------------
__device__ float  g_h   [N_NODES * DIM];
__device__ float  g_e   [N_EDGES * DIM];
__device__ float  g_abde[N_NODES * 4 * DIM];
__device__ float  g_enew[N_EDGES * DIM];
__device__ float  g_hnew[N_NODES * DIM];
__device__ double g_stats[4 * DIM];
__device__ float  g_bn  [4 * DIM];
__device__ int    g_cnt [N_NODES];
__device__ int    g_cnt2[N_NODES];
__device__ int    g_csr [N_NODES + 1];
__device__ int    g_perm[N_EDGES];
__device__ int    g_srcp[N_EDGES];
__device__ uint32_t g_wimg[22 * IMG_U32];
__device__ int    g_hmma_ok;

// ---------------- bf16 helpers ----------------
__device__ __forceinline__ uint32_t pack2(float a, float b) {
    uint32_t r; asm("cvt.rn.bf16x2.f32 %0, %1, %2;" : "=r"(r) : "f"(b), "f"(a)); return r;
}
__device__ __forceinline__ void split2(float a, float b, uint32_t& hi, uint32_t& lo) {
    hi = pack2(a, b);
    float ha = __uint_as_float(hi << 16);
    float hb = __uint_as_float(hi & 0xffff0000u);
    lo = pack2(a - ha, b - hb);
}
__device__ __forceinline__ void mma16816(float (&d)[4], const uint32_t (&a)[4],
                                         const uint32_t b0, const uint32_t b1) {
    asm volatile("mma.sync.aligned.m16n8k16.row.col.f32.bf16.bf16.f32 "
        "{%0,%1,%2,%3}, {%4,%5,%6,%7}, {%8,%9}, {%0,%1,%2,%3};"
        : "+f"(d[0]), "+f"(d[1]), "+f"(d[2]), "+f"(d[3])
        : "r"(a[0]), "r"(a[1]), "r"(a[2]), "r"(a[3]), "r"(b0), "r"(b1));
}
__device__ __forceinline__ void ldsm_x4(uint32_t (&r)[4], uint32_t saddr) {
    asm volatile("ldmatrix.sync.aligned.m8n8.x4.shared.b16 {%0,%1,%2,%3}, [%4];"
        : "=r"(r[0]), "=r"(r[1]), "=r"(r[2]), "=r"(r[3]) : "r"(saddr));
}

// ================= numeric HMMA probe =================
__global__ void k_probe() {
    uint32_t one2 = 0x3f803f80u;
    uint32_t a[4] = {one2, one2, one2, one2};
    float d[4] = {0.f, 0.f, 0.f, 0.f};
    mma16816(d, a, one2, one2);
    bool ok = (d[0] == 16.f) && (d[1] == 16.f) && (d[2] == 16.f) && (d[3] == 16.f);
    unsigned m = __ballot_sync(0xffffffffu, ok);
    if ((threadIdx.x & 31) == 0) g_hmma_ok = (m == 0xffffffffu) ? 1 : 0;
}

// ---------------- weight prep ----------------
__global__ void k_prep_w(const float* Wh, const float* We,
                         const float* Aw, const float* Bw, const float* Cw,
                         const float* Dw, const float* Ew)
{
    int bx = blockIdx.x;
    const float* W;
    if (bx == 0) W = Wh;
    else if (bx == 1) W = We;
    else {
        int i = bx - 2, l = i / 5, w = i % 5;
        W = ((w == 0) ? Aw : (w == 1) ? Bw : (w == 2) ? Cw : (w == 3) ? Dw : Ew) + (size_t)l * DD;
    }
    uint32_t* img = &g_wimg[(size_t)bx * IMG_U32];
    for (int p = threadIdx.x; p < 8192; p += blockDim.x) {
        int n = p >> 6, kp = p & 63, k = kp << 1;
        uint32_t hi, lo;
        split2(W[k * DIM + n], W[(k + 1) * DIM + n], hi, lo);
        img[n * 64 + kp] = hi;
        img[8192 + n * 64 + kp] = lo;
    }
}

// ================= SIMT fp32 mainloop (fallback; uses dynamic smem region) =================
__device__ __forceinline__ void gemm_mainloop(
    const float* __restrict__ A, const float* __restrict__ B,
    int M, int row0, float (&acc)[8][8],
    float (*As)[16][DIM], float (*Bs)[16][DIM])
{
    const int tid = threadIdx.x;
    const int ty = tid >> 4, tx = tid & 15;
    const int ar0 = tid >> 2, ac0 = (tid & 3) << 2;
    const int ar1 = ar0 + 64;
    const int br0 = tid >> 5, bc0 = (tid & 31) << 2;
    const int br1 = br0 + 8;
    const int r0 = row0 + ar0, r1 = row0 + ar1;
    const float4 z4 = make_float4(0.f, 0.f, 0.f, 0.f);
    float4 av0, av1, bv0, bv1;

    av0 = (r0 < M) ? *(const float4*)&A[(size_t)r0 * DIM + ac0] : z4;
    av1 = (r1 < M) ? *(const float4*)&A[(size_t)r1 * DIM + ac0] : z4;
    bv0 = *(const float4*)&B[br0 * DIM + bc0];
    bv1 = *(const float4*)&B[br1 * DIM + bc0];
    As[0][ac0+0][ar0] = av0.x; As[0][ac0+1][ar0] = av0.y; As[0][ac0+2][ar0] = av0.z; As[0][ac0+3][ar0] = av0.w;
    As[0][ac0+0][ar1] = av1.x; As[0][ac0+1][ar1] = av1.y; As[0][ac0+2][ar1] = av1.z; As[0][ac0+3][ar1] = av1.w;
    *(float4*)&Bs[0][br0][bc0] = bv0;
    *(float4*)&Bs[0][br1][bc0] = bv1;
    __syncthreads();

    av0 = (r0 < M) ? *(const float4*)&A[(size_t)r0 * DIM + 16 + ac0] : z4;
    av1 = (r1 < M) ? *(const float4*)&A[(size_t)r1 * DIM + 16 + ac0] : z4;
    bv0 = *(const float4*)&B[(16 + br0) * DIM + bc0];
    bv1 = *(const float4*)&B[(16 + br1) * DIM + bc0];

    #pragma unroll 1
    for (int it = 0; it < 8; it++) {
        const int cur = it & 1;
        #pragma unroll
        for (int k = 0; k < 16; k++) {
            float a[8], b[8];
            *(float4*)(a)   = *(const float4*)&As[cur][k][ty*8];
            *(float4*)(a+4) = *(const float4*)&As[cur][k][ty*8+4];
            *(float4*)(b)   = *(const float4*)&Bs[cur][k][tx*8];
            *(float4*)(b+4) = *(const float4*)&Bs[cur][k][tx*8+4];
            #pragma unroll
            for (int i = 0; i < 8; i++)
                #pragma unroll
                for (int j = 0; j < 8; j++)
                    acc[i][j] = fmaf(a[i], b[j], acc[i][j]);
        }
        if (it < 7) {
            const int nxt = cur ^ 1;
            As[nxt][ac0+0][ar0] = av0.x; As[nxt][ac0+1][ar0] = av0.y; As[nxt][ac0+2][ar0] = av0.z; As[nxt][ac0+3][ar0] = av0.w;
            As[nxt][ac0+0][ar1] = av1.x; As[nxt][ac0+1][ar1] = av1.y; As[nxt][ac0+2][ar1] = av1.z; As[nxt][ac0+3][ar1] = av1.w;
            *(float4*)&Bs[nxt][br0][bc0] = bv0;
            *(float4*)&Bs[nxt][br1][bc0] = bv1;
            __syncthreads();
            if (it < 6) {
                int kk = (it + 2) * 16;
                av0 = (r0 < M) ? *(const float4*)&A[(size_t)r0 * DIM + kk + ac0] : z4;
                av1 = (r1 < M) ? *(const float4*)&A[(size_t)r1 * DIM + kk + ac0] : z4;
                bv0 = *(const float4*)&B[(kk + br0) * DIM + bc0];
                bv1 = *(const float4*)&B[(kk + br1) * DIM + bc0];
            }
        }
    }
}

// ================= HMMA pieces: full-K A residency =================
// convert A rows [row0,row0+128) full K into dsm A region (one pass)
__device__ __forceinline__ void hmma_convert_A_full(
    const float* __restrict__ Asrc, int M, int row0, uint32_t* dsm)
{
    int tid = threadIdx.x;
    #pragma unroll
    for (int q = 0; q < 32; q++) {
        int p = tid + q * 256;
        int row = p >> 6, kw = p & 63;
        int r = row0 + row;
        float2 v = (r < M) ? *(const float2*)&Asrc[(size_t)r * DIM + kw * 2]
                           : make_float2(0.f, 0.f);
        uint32_t hi, lo;
        split2(v.x, v.y, hi, lo);
        dsm[row * RSA + kw] = hi;
        dsm[A_SPLIT_OFF + row * RSA + kw] = lo;
    }
}
__device__ __forceinline__ void hmma_copy_Bslice(
    const uint32_t* __restrict__ wimg, int it, uint32_t* dsm)
{
    int tid = threadIdx.x;
    #pragma unroll
    for (int q = 0; q < 8; q++) {
        int p = tid + q * 256;
        int n = p >> 4, kpl = p & 15;
        dsm[B_BASE + n * RS2 + kpl] = wimg[n * 64 + it * 16 + kpl];
        dsm[B_BASE + B_SPLIT_OFF + n * RS2 + kpl] = wimg[8192 + n * 64 + it * 16 + kpl];
    }
}
// MMA over all 4 B-slices of one weight; A already resident full-K
__device__ __forceinline__ void hmma_weight_loop(
    const uint32_t* __restrict__ wimg, uint32_t* dsm, float (&acc)[2][8][4])
{
    int tid = threadIdx.x, lid = tid & 31, wid = tid >> 5;
    int wm = wid & 3, wn = wid >> 2;
    int lrow = lid & 7, lj = lid >> 3;
    int a_row_off = ((lj & 1) << 3) + lrow;
    int a_word    = (lj >> 1) << 2;
    int b_row_off = ((lj >> 1) << 3) + lrow;
    int b_word    = (lj & 1) << 2;
    uint32_t sA0 = (uint32_t)__cvta_generic_to_shared(dsm);
    uint32_t sA1 = (uint32_t)__cvta_generic_to_shared(dsm + A_SPLIT_OFF);
    uint32_t sB0 = (uint32_t)__cvta_generic_to_shared(dsm + B_BASE);
    uint32_t sB1 = (uint32_t)__cvta_generic_to_shared(dsm + B_BASE + B_SPLIT_OFF);

    #pragma unroll 1
    for (int it = 0; it < 4; it++) {
        __syncthreads();                 // prior MMA done reading B (or A ready at it=0)
        hmma_copy_Bslice(wimg, it, dsm);
        __syncthreads();
        #pragma unroll
        for (int kk = 0; kk < 2; kk++) {
            uint32_t ah[2][4], al[2][4];
            #pragma unroll
            for (int mi = 0; mi < 2; mi++) {
                uint32_t off = (uint32_t)(((wm * 32 + mi * 16 + a_row_off) * RSA
                                           + it * 16 + kk * 8 + a_word) * 4);
                ldsm_x4(ah[mi], sA0 + off);
                ldsm_x4(al[mi], sA1 + off);
            }
            #pragma unroll
            for (int np = 0; np < 4; np++) {
                uint32_t off = (uint32_t)(((wn * 64 + np * 16 + b_row_off) * RS2
                                           + kk * 8 + b_word) * 4);
                uint32_t bh[4], bl[4];
                ldsm_x4(bh, sB0 + off);
                ldsm_x4(bl, sB1 + off);
                #pragma unroll
                for (int s = 0; s < 2; s++) {
                    int ni = np * 2 + s;
                    #pragma unroll
                    for (int mi = 0; mi < 2; mi++) {
                        mma16816(acc[mi][ni], ah[mi], bh[s*2], bh[s*2+1]);
                        mma16816(acc[mi][ni], ah[mi], bl[s*2], bl[s*2+1]);
                        mma16816(acc[mi][ni], al[mi], bh[s*2], bh[s*2+1]);
                    }
                }
            }
        }
    }
}
__device__ __forceinline__ void hmma_store(
    float (&acc)[2][8][4], int M, int row0, float* __restrict__ out, int ldc, int cbase,
    const float* __restrict__ s_bias)
{
    int tid = threadIdx.x, lid = tid & 31, wid = tid >> 5;
    int g = lid >> 2, t = lid & 3;
    int wm = wid & 3, wn = wid >> 2;
    #pragma unroll
    for (int mi = 0; mi < 2; mi++)
        #pragma unroll
        for (int hf = 0; hf < 2; hf++) {
            int r = row0 + wm * 32 + mi * 16 + hf * 8 + g;
            if (r < M) {
                #pragma unroll
                for (int ni = 0; ni < 8; ni++) {
                    int c = wn * 64 + ni * 8 + t * 2;
                    *(float2*)&out[(size_t)r * ldc + cbase + c] = make_float2(
                        acc[mi][ni][hf * 2 + 0] + s_bias[c],
                        acc[mi][ni][hf * 2 + 1] + s_bias[c + 1]);
                }
            }
        }
}

// ---------------- unified GEMM (embeddings) ----------------
__global__ void __launch_bounds__(256, 2) k_gemm_plain(
    const float* __restrict__ A, const float* __restrict__ W, int widx,
    const float* __restrict__ bias, int M, int which)
{
    extern __shared__ uint32_t dsm[];
    __shared__ float s_bias[DIM];
    int tid = threadIdx.x;
    int row0 = blockIdx.x * 128;
    float* out = which ? g_e : g_h;
    if (tid < DIM) s_bias[tid] = bias[tid];

    if (g_hmma_ok) {
        float acc[2][8][4] = {};
        hmma_convert_A_full(A, M, row0, dsm);
        hmma_weight_loop(&g_wimg[(size_t)widx * IMG_U32], dsm, acc);
        hmma_store(acc, M, row0, out, DIM, 0, s_bias);
    } else {
        float (*As)[16][DIM] = reinterpret_cast<float(*)[16][DIM]>(dsm);
        float (*Bs)[16][DIM] = reinterpret_cast<float(*)[16][DIM]>(dsm + 4096);
        float acc[8][8] = {};
        __syncthreads();
        gemm_mainloop(A, W, M, row0, acc, As, Bs);
        int tx = tid & 15, ty = tid >> 4;
        int c0 = tx * 8;
        #pragma unroll
        for (int i = 0; i < 8; i++) {
            int r = row0 + ty*8 + i;
            if (r < M) {
                #pragma unroll
                for (int j = 0; j < 8; j++)
                    out[(size_t)r * DIM + c0 + j] = acc[i][j] + s_bias[c0 + j];
            }
        }
    }
}

// ---------------- node GEMM: ONE CTA computes A,B,D,E outputs (A converted once) ----------------
__global__ void __launch_bounds__(256, 2) k_gemm_node4(
    int l, const float* __restrict__ Aw, const float* __restrict__ Bw,
    const float* __restrict__ Dw, const float* __restrict__ Ew,
    const float* __restrict__ Ab, const float* __restrict__ Bb,
    const float* __restrict__ Db, const float* __restrict__ Eb)
{
    extern __shared__ uint32_t dsm[];
    __shared__ float s_bias[4 * DIM];
    int tid = threadIdx.x;
    int row0 = blockIdx.x * 128;
    int base = 2 + l * 5;
    const int widx[4] = {base + 0, base + 1, base + 3, base + 4};  // A,B,D,E

    if (tid < DIM) {
        s_bias[tid] = Ab[tid]; s_bias[DIM + tid] = Bb[tid];
        s_bias[2*DIM + tid] = Db[tid]; s_bias[3*DIM + tid] = Eb[tid];
    }

    if (g_hmma_ok) {
        hmma_convert_A_full(g_h, N_NODES, row0, dsm);
        for (int y = 0; y < 4; y++) {
            float acc[2][8][4] = {};
            hmma_weight_loop(&g_wimg[(size_t)widx[y] * IMG_U32], dsm, acc);
            hmma_store(acc, N_NODES, row0, g_abde, 512, y * DIM, &s_bias[y * DIM]);
        }
    } else {
        float (*As)[16][DIM] = reinterpret_cast<float(*)[16][DIM]>(dsm);
        float (*Bs)[16][DIM] = reinterpret_cast<float(*)[16][DIM]>(dsm + 4096);
        int tx = tid & 15, ty = tid >> 4;
        int c0 = tx * 8;
        for (int y = 0; y < 4; y++) {
            const float* W = (y == 0) ? Aw : (y == 1) ? Bw : (y == 2) ? Dw : Ew;
            float acc[8][8] = {};
            __syncthreads();
            gemm_mainloop(g_h, W, N_NODES, row0, acc, As, Bs);
            #pragma unroll
            for (int i = 0; i < 8; i++) {
                int r = row0 + ty*8 + i;
                if (r < N_NODES) {
                    #pragma unroll
                    for (int j = 0; j < 8; j++)
                        g_abde[(size_t)r * 512 + y * DIM + c0 + j] = acc[i][j] + s_bias[y*DIM + c0 + j];
                }
            }
            __syncthreads();
        }
    }
}

// ---------------- edge GEMM + gather + (optional) e-BN stats ----------------
__global__ void __launch_bounds__(256, 2) k_gemm_edge(
    int l, const float* __restrict__ Cw, const float* __restrict__ Cb,
    const int* __restrict__ src, const int* __restrict__ dst, int do_estats)
{
    extern __shared__ uint32_t dsm[];
    __shared__ float s_cb[DIM], s_sum[DIM], s_sq[DIM];
    int tid = threadIdx.x, lid = tid & 31, wid = tid >> 5;
    int row0 = blockIdx.x * 128;
    if (tid < DIM) { s_cb[tid] = Cb[tid]; s_sum[tid] = 0.f; s_sq[tid] = 0.f; }

    if (g_hmma_ok) {
        int g = lid >> 2, t = lid & 3;
        int wm = wid & 3, wn = wid >> 2;
        float acc[2][8][4] = {};
        hmma_convert_A_full(g_e, N_EDGES, row0, dsm);
        hmma_weight_loop(&g_wimg[(size_t)(2 + l * 5 + 2) * IMG_U32], dsm, acc);

        int rows[4], svr[4], dvr[4];
        #pragma unroll
        for (int ridx = 0; ridx < 4; ridx++) {
            int mi = ridx >> 1, hf = ridx & 1;
            rows[ridx] = row0 + wm * 32 + mi * 16 + hf * 8 + g;
            svr[ridx] = src[rows[ridx]];
            dvr[ridx] = dst[rows[ridx]];
        }
        #pragma unroll
        for (int ni = 0; ni < 8; ni++) {
            int c = wn * 64 + ni * 8 + t * 2;
            float cb0 = s_cb[c], cb1 = s_cb[c + 1];
            float s0 = 0.f, s1 = 0.f, q0 = 0.f, q1 = 0.f;
            #pragma unroll
            for (int ridx = 0; ridx < 4; ridx++) {
                int mi = ridx >> 1, hf = ridx & 1;
                float2 dD = *(const float2*)&g_abde[(size_t)svr[ridx] * 512 + 256 + c];
                float2 dE = *(const float2*)&g_abde[(size_t)dvr[ridx] * 512 + 384 + c];
                float v0 = acc[mi][ni][hf * 2 + 0] + cb0 + dD.x + dE.x;
                float v1 = acc[mi][ni][hf * 2 + 1] + cb1 + dD.y + dE.y;
                *(float2*)&g_enew[(size_t)rows[ridx] * DIM + c] = make_float2(v0, v1);
                s0 += v0; q0 += v0 * v0;
                s1 += v1; q1 += v1 * v1;
            }
            if (do_estats) {
                #pragma unroll
                for (int s = 4; s < 32; s <<= 1) {
                    s0 += __shfl_xor_sync(0xffffffffu, s0, s);
                    s1 += __shfl_xor_sync(0xffffffffu, s1, s);
                    q0 += __shfl_xor_sync(0xffffffffu, q0, s);
                    q1 += __shfl_xor_sync(0xffffffffu, q1, s);
                }
                if (g == 0) {
                    atomicAdd(&s_sum[c], s0);     atomicAdd(&s_sq[c], q0);
                    atomicAdd(&s_sum[c + 1], s1); atomicAdd(&s_sq[c + 1], q1);
                }
            }
        }
    } else {
        float (*As)[16][DIM] = reinterpret_cast<float(*)[16][DIM]>(dsm);
        float (*Bs)[16][DIM] = reinterpret_cast<float(*)[16][DIM]>(dsm + 4096);
        float acc[8][8] = {};
        __syncthreads();
        gemm_mainloop(g_e, Cw, N_EDGES, row0, acc, As, Bs);
        __syncthreads();
        int tx = tid & 15, ty = tid >> 4;
        int c0 = tx * 8;
        float cb[8];
        #pragma unroll
        for (int j = 0; j < 8; j++) cb[j] = s_cb[c0 + j];
        float csum[8] = {}, csq[8] = {};
        #pragma unroll 1
        for (int i = 0; i < 8; i++) {
            int r = row0 + ty*8 + i;
            int sv = src[r], dv = dst[r];
            const float* Dp = &g_abde[(size_t)sv * 512 + 256 + c0];
            const float* Ep = &g_abde[(size_t)dv * 512 + 384 + c0];
            float dh[8], eh[8], ev[8];
            *(float4*)(dh)   = *(const float4*)(Dp);
            *(float4*)(dh+4) = *(const float4*)(Dp+4);
            *(float4*)(eh)   = *(const float4*)(Ep);
            *(float4*)(eh+4) = *(const float4*)(Ep+4);
            #pragma unroll
            for (int j = 0; j < 8; j++) {
                float v = acc[i][j] + cb[j] + dh[j] + eh[j];
                ev[j] = v;
                csum[j] += v;
                csq[j]  += v * v;
            }
            *(float4*)&g_enew[(size_t)r * DIM + c0]     = *(float4*)(ev);
            *(float4*)&g_enew[(size_t)r * DIM + c0 + 4] = *(float4*)(ev+4);
        }
        if (do_estats) {
            #pragma unroll
            for (int j = 0; j < 8; j++) {
                atomicAdd(&s_sum[c0 + j], csum[j]);
                atomicAdd(&s_sq[c0 + j],  csq[j]);
            }
        }
    }
    __syncthreads();
    if (do_estats && tid < DIM) {
        atomicAdd(&g_stats[2*DIM + tid], (double)s_sum[tid]);
        atomicAdd(&g_stats[3*DIM + tid], (double)s_sq[tid]);
    }
}

// ================= CSR build =================
__global__ void k_zero_cnt() {
    int i = blockIdx.x * blockDim.x + threadIdx.x;
    if (i < N_NODES) { g_cnt[i] = 0; g_cnt2[i] = 0; }
}
__global__ void k_hist(const int* __restrict__ dst) {
    int e = blockIdx.x * blockDim.x + threadIdx.x;
    if (e < N_EDGES) atomicAdd(&g_cnt[dst[e]], 1);
}
__global__ void k_scan() {
    __shared__ int s[1024];
    int tn = threadIdx.x;
    int base = tn * 20;
    int loc[20];
    int sum = 0;
    #pragma unroll
    for (int j = 0; j < 20; j++) {
        int idx = base + j;
        loc[j] = sum;
        if (idx < N_NODES) sum += g_cnt[idx];
    }
    s[tn] = sum;
    __syncthreads();
    for (int off = 1; off < 1024; off <<= 1) {
        int v = (tn >= off) ? s[tn - off] : 0;
        __syncthreads();
        s[tn] += v;
        __syncthreads();
    }
    int pre = (tn > 0) ? s[tn - 1] : 0;
    #pragma unroll
    for (int j = 0; j < 20; j++) {
        int idx = base + j;
        if (idx < N_NODES) g_csr[idx] = pre + loc[j];
    }
    if (tn == 1023) g_csr[N_NODES] = s[1023];
}
__global__ void k_scatter(const int* __restrict__ src, const int* __restrict__ dst) {
    int e = blockIdx.x * blockDim.x + threadIdx.x;
    if (e < N_EDGES) {
        int d = dst[e];
        int pos = g_csr[d] + atomicAdd(&g_cnt2[d], 1);
        g_perm[pos] = e;
        g_srcp[pos] = src[e];
    }
}
__global__ void k_zero_stats() {
    int i = threadIdx.x;
    if (i < 4 * DIM) g_stats[i] = 0.0;
}

// ---------------- per-node aggregation (round-11 semantics; no fusion) ----------------
__global__ void __launch_bounds__(128) k_aggregate() {
    int n = blockIdx.x;
    int t = threadIdx.x;
    int beg = g_csr[n], end = g_csr[n + 1];
    float num = 0.f, den = 0.f;
    for (int i = beg; i < end; i++) {
        int e = g_perm[i];
        int s = g_srcp[i];
        float v = g_enew[(size_t)e * DIM + t];
        float bh = g_abde[(size_t)s * 512 + 128 + t];
        float sg = 1.f / (1.f + __expf(-v));
        num = fmaf(sg, bh, num);
        den += sg;
    }
    float hv = g_abde[(size_t)n * 512 + t] + num / (den + 1e-6f);
    g_hnew[n * DIM + t] = hv;
}

__global__ void __launch_bounds__(256) k_hstats() {
    __shared__ float s_sum[DIM];
    __shared__ float s_sq[DIM];
    int tid = threadIdx.x;
    if (tid < DIM) { s_sum[tid] = 0.f; s_sq[tid] = 0.f; }
    __syncthreads();
    int col = tid & 127;
    int rh = tid >> 7;
    int row0 = blockIdx.x * 128;
    float ls = 0.f, lq = 0.f;
    for (int i = rh; i < 128; i += 2) {
        int r = row0 + i;
        if (r < N_NODES) {
            float v = g_hnew[r * DIM + col];
            ls += v; lq += v * v;
        }
    }
    atomicAdd(&s_sum[col], ls);
    atomicAdd(&s_sq[col], lq);
    __syncthreads();
    if (tid < DIM) {
        atomicAdd(&g_stats[tid],       (double)s_sum[tid]);
        atomicAdd(&g_stats[DIM + tid], (double)s_sq[tid]);
    }
}

// finalize both BN param sets (e part optional) and reset stats for next layer
__global__ void k_finalize(const float* __restrict__ gh, const float* __restrict__ bh,
                           const float* __restrict__ ge, const float* __restrict__ be,
                           int do_e)
{
    int t = threadIdx.x;
    if (t < DIM) {
        double mu  = g_stats[t] / (double)N_NODES;
        double var = g_stats[DIM + t] / (double)N_NODES - mu * mu;
        double rstd = 1.0 / sqrt(var + 1e-5);
        float sc = gh[t] * (float)rstd;
        g_bn[t] = sc;
        g_bn[DIM + t] = bh[t] - (float)mu * sc;
    } else if (t < 2 * DIM && do_e) {
        int c = t - DIM;
        double mu  = g_stats[2*DIM + c] / (double)N_EDGES;
        double var = g_stats[3*DIM + c] / (double)N_EDGES - mu * mu;
        double rstd = 1.0 / sqrt(var + 1e-5);
        float sc = ge[c] * (float)rstd;
        g_bn[2*DIM + c] = sc;
        g_bn[3*DIM + c] = be[c] - (float)mu * sc;
    }
    __syncthreads();
    g_stats[t] = 0.0;
    g_stats[t + 256] = 0.0;
}

__global__ void k_apply_h() {
    int i4 = blockIdx.x * blockDim.x + threadIdx.x;
    if (i4 < N_NODES * DIM / 4) {
        int c4 = (i4 & 31) * 4;
        float4 v  = *(const float4*)&g_hnew[i4 * 4];
        float4 sc = *(const float4*)&g_bn[c4];
        float4 sh = *(const float4*)&g_bn[DIM + c4];
        float4 hv = *(const float4*)&g_h[i4 * 4];
        hv.x += fmaxf(fmaf(v.x, sc.x, sh.x), 0.f);
        hv.y += fmaxf(fmaf(v.y, sc.y, sh.y), 0.f);
        hv.z += fmaxf(fmaf(v.z, sc.z, sh.z), 0.f);
        hv.w += fmaxf(fmaf(v.w, sc.w, sh.w), 0.f);
        *(float4*)&g_h[i4 * 4] = hv;
    }
}
__global__ void k_apply_e() {
    int i4 = blockIdx.x * blockDim.x + threadIdx.x;
    if (i4 < N_EDGES * DIM / 4) {
        int c4 = (i4 & 31) * 4;
        float4 v  = *(const float4*)&g_enew[(size_t)i4 * 4];
        float4 sc = *(const float4*)&g_bn[2*DIM + c4];
        float4 sh = *(const float4*)&g_bn[3*DIM + c4];
        float4 evv = *(const float4*)&g_e[(size_t)i4 * 4];
        evv.x += fmaxf(fmaf(v.x, sc.x, sh.x), 0.f);
        evv.y += fmaxf(fmaf(v.y, sc.y, sh.y), 0.f);
        evv.z += fmaxf(fmaf(v.z, sc.z, sh.z), 0.f);
        evv.w += fmaxf(fmaf(v.w, sc.w, sh.w), 0.f);
        *(float4*)&g_e[(size_t)i4 * 4] = evv;
    }
}

// ---------------- host launch ----------------
extern "C" void kernel_launch(void* const* d_in, const int* in_sizes, int n_in,
                              void* d_out, int out_size)
{
    const float* h0  = (const float*)d_in[0];
    const float* e0  = (const float*)d_in[1];
    const int*   src = (const int*)  d_in[2];
    const int*   dst = (const int*)  d_in[3];
    const float* Wh  = (const float*)d_in[4];
    const float* bhe = (const float*)d_in[5];
    const float* We  = (const float*)d_in[6];
    const float* bee = (const float*)d_in[7];
    const float* Aw  = (const float*)d_in[8];
    const float* Ab  = (const float*)d_in[9];
    const float* Bw  = (const float*)d_in[10];
    const float* Bb  = (const float*)d_in[11];
    const float* Cw  = (const float*)d_in[12];
    const float* Cb  = (const float*)d_in[13];
    const float* Dw  = (const float*)d_in[14];
    const float* Db  = (const float*)d_in[15];
    const float* Ew  = (const float*)d_in[16];
    const float* Eb  = (const float*)d_in[17];
    const float* gh  = (const float*)d_in[18];
    const float* bh  = (const float*)d_in[19];
    const float* ge  = (const float*)d_in[20];
    const float* be  = (const float*)d_in[21];

    const int grid_node = (N_NODES + 127) / 128;   // 157
    const int grid_edge = N_EDGES / 128;           // 2000

    cudaFuncSetAttribute(k_gemm_plain, cudaFuncAttributeMaxDynamicSharedMemorySize, DYN_BYTES);
    cudaFuncSetAttribute(k_gemm_node4, cudaFuncAttributeMaxDynamicSharedMemorySize, DYN_BYTES);
    cudaFuncSetAttribute(k_gemm_edge,  cudaFuncAttributeMaxDynamicSharedMemorySize, DYN_BYTES);

    // launch #4 = edge-embedding HMMA GEMM -> the kernel ncu displays
    k_probe<<<1, 32>>>();
    k_prep_w<<<22, 256>>>(Wh, We, Aw, Bw, Cw, Dw, Ew);
    k_gemm_plain<<<grid_node, 256, DYN_BYTES>>>(h0, Wh, 0, bhe, N_NODES, 0);
    k_gemm_plain<<<grid_edge, 256, DYN_BYTES>>>(e0, We, 1, bee, N_EDGES, 1);

    k_zero_cnt<<<(N_NODES + 255) / 256, 256>>>();
    k_hist<<<(N_EDGES + 255) / 256, 256>>>(dst);
    k_scan<<<1, 1024>>>();
    k_scatter<<<(N_EDGES + 255) / 256, 256>>>(src, dst);
    k_zero_stats<<<1, 512>>>();

    for (int l = 0; l < 4; l++) {
        int do_e = (l < 3) ? 1 : 0;   // e_3 dead: no stats/finalize/apply
        k_gemm_node4<<<grid_node, 256, DYN_BYTES>>>(l,
            Aw + l*DD, Bw + l*DD, Dw + l*DD, Ew + l*DD,
            Ab + l*DIM, Bb + l*DIM, Db + l*DIM, Eb + l*DIM);
        k_gemm_edge<<<grid_edge, 256, DYN_BYTES>>>(l, Cw + l*DD, Cb + l*DIM, src, dst, do_e);
        k_aggregate<<<N_NODES, 128>>>();
        k_hstats<<<grid_node, 256>>>();
        k_finalize<<<1, 256>>>(gh + l*DIM, bh + l*DIM, ge + l*DIM, be + l*DIM, do_e);
        k_apply_h<<<(N_NODES * DIM / 4 + 255) / 256, 256>>>();
        if (do_e)
            k_apply_e<<<(N_EDGES * DIM / 4 + 255) / 256, 256>>>();
    }

    cudaMemcpyFromSymbolAsync(d_out, g_h, sizeof(float) * N_NODES * DIM, 0,
                              cudaMemcpyDeviceToDevice, 0);
}

// round 14
// speedup vs baseline: 1.0353x; 1.0207x over previous
#include <cuda_runtime.h>
#include <cstdint>

#define N_NODES 20000
#define N_EDGES 256000
#define DIM 128
#define DD (DIM*DIM)

#define RS2 20                       // BK=32 smem row stride (u32)
#define RSA 68                       // full-K A smem row stride (u32)
#define IMG_U32 16384                // per-matrix bf16 image (8192 hi + 8192 lo)
#define UNION_U32 10240              // 40KB static smem union (edge/plain kernels)
#define A_SPLIT_OFF (128 * RSA)      // 8704
#define B_BASE      (2 * 128 * RSA)  // 17408
#define B_SPLIT_OFF (128 * RS2)      // 2560
#define DYN_U32   (B_BASE + 2 * B_SPLIT_OFF)
#define DYN_BYTES (DYN_U32 * 4)      // 90112 B (node kernel only)

// ---------------- static device scratch ----------------
__device__ float  g_h   [N_NODES * DIM];
__device__ float  g_e   [N_EDGES * DIM];
__device__ float  g_abde[N_NODES * 4 * DIM];
__device__ float  g_enew[N_EDGES * DIM];
__device__ float  g_hnew[N_NODES * DIM];
__device__ double g_stats[4 * DIM];
__device__ float  g_bn  [4 * DIM];
__device__ int    g_cnt [N_NODES];
__device__ int    g_cnt2[N_NODES];
__device__ int    g_csr [N_NODES + 1];
__device__ int    g_perm[N_EDGES];
__device__ int    g_srcp[N_EDGES];
__device__ uint32_t g_wimg[22 * IMG_U32];
__device__ int    g_hmma_ok;

// ---------------- bf16 helpers ----------------
__device__ __forceinline__ uint32_t pack2(float a, float b) {
    uint32_t r; asm("cvt.rn.bf16x2.f32 %0, %1, %2;" : "=r"(r) : "f"(b), "f"(a)); return r;
}
__device__ __forceinline__ void split2(float a, float b, uint32_t& hi, uint32_t& lo) {
    hi = pack2(a, b);
    float ha = __uint_as_float(hi << 16);
    float hb = __uint_as_float(hi & 0xffff0000u);
    lo = pack2(a - ha, b - hb);
}
__device__ __forceinline__ void mma16816(float (&d)[4], const uint32_t (&a)[4],
                                         const uint32_t b0, const uint32_t b1) {
    asm volatile("mma.sync.aligned.m16n8k16.row.col.f32.bf16.bf16.f32 "
        "{%0,%1,%2,%3}, {%4,%5,%6,%7}, {%8,%9}, {%0,%1,%2,%3};"
        : "+f"(d[0]), "+f"(d[1]), "+f"(d[2]), "+f"(d[3])
        : "r"(a[0]), "r"(a[1]), "r"(a[2]), "r"(a[3]), "r"(b0), "r"(b1));
}
__device__ __forceinline__ void ldsm_x4(uint32_t (&r)[4], uint32_t saddr) {
    asm volatile("ldmatrix.sync.aligned.m8n8.x4.shared.b16 {%0,%1,%2,%3}, [%4];"
        : "=r"(r[0]), "=r"(r[1]), "=r"(r[2]), "=r"(r[3]) : "r"(saddr));
}

// ================= numeric HMMA probe =================
__global__ void k_probe() {
    uint32_t one2 = 0x3f803f80u;
    uint32_t a[4] = {one2, one2, one2, one2};
    float d[4] = {0.f, 0.f, 0.f, 0.f};
    mma16816(d, a, one2, one2);
    bool ok = (d[0] == 16.f) && (d[1] == 16.f) && (d[2] == 16.f) && (d[3] == 16.f);
    unsigned m = __ballot_sync(0xffffffffu, ok);
    if ((threadIdx.x & 31) == 0) g_hmma_ok = (m == 0xffffffffu) ? 1 : 0;
}

// ---------------- weight prep ----------------
__global__ void k_prep_w(const float* Wh, const float* We,
                         const float* Aw, const float* Bw, const float* Cw,
                         const float* Dw, const float* Ew)
{
    int bx = blockIdx.x;
    const float* W;
    if (bx == 0) W = Wh;
    else if (bx == 1) W = We;
    else {
        int i = bx - 2, l = i / 5, w = i % 5;
        W = ((w == 0) ? Aw : (w == 1) ? Bw : (w == 2) ? Cw : (w == 3) ? Dw : Ew) + (size_t)l * DD;
    }
    uint32_t* img = &g_wimg[(size_t)bx * IMG_U32];
    for (int p = threadIdx.x; p < 8192; p += blockDim.x) {
        int n = p >> 6, kp = p & 63, k = kp << 1;
        uint32_t hi, lo;
        split2(W[k * DIM + n], W[(k + 1) * DIM + n], hi, lo);
        img[n * 64 + kp] = hi;
        img[8192 + n * 64 + kp] = lo;
    }
}

// ================= SIMT fp32 mainloop (fallback) =================
__device__ __forceinline__ void gemm_mainloop(
    const float* __restrict__ A, const float* __restrict__ B,
    int M, int row0, float (&acc)[8][8],
    float (*As)[16][DIM], float (*Bs)[16][DIM])
{
    const int tid = threadIdx.x;
    const int ty = tid >> 4, tx = tid & 15;
    const int ar0 = tid >> 2, ac0 = (tid & 3) << 2;
    const int ar1 = ar0 + 64;
    const int br0 = tid >> 5, bc0 = (tid & 31) << 2;
    const int br1 = br0 + 8;
    const int r0 = row0 + ar0, r1 = row0 + ar1;
    const float4 z4 = make_float4(0.f, 0.f, 0.f, 0.f);
    float4 av0, av1, bv0, bv1;

    av0 = (r0 < M) ? *(const float4*)&A[(size_t)r0 * DIM + ac0] : z4;
    av1 = (r1 < M) ? *(const float4*)&A[(size_t)r1 * DIM + ac0] : z4;
    bv0 = *(const float4*)&B[br0 * DIM + bc0];
    bv1 = *(const float4*)&B[br1 * DIM + bc0];
    As[0][ac0+0][ar0] = av0.x; As[0][ac0+1][ar0] = av0.y; As[0][ac0+2][ar0] = av0.z; As[0][ac0+3][ar0] = av0.w;
    As[0][ac0+0][ar1] = av1.x; As[0][ac0+1][ar1] = av1.y; As[0][ac0+2][ar1] = av1.z; As[0][ac0+3][ar1] = av1.w;
    *(float4*)&Bs[0][br0][bc0] = bv0;
    *(float4*)&Bs[0][br1][bc0] = bv1;
    __syncthreads();

    av0 = (r0 < M) ? *(const float4*)&A[(size_t)r0 * DIM + 16 + ac0] : z4;
    av1 = (r1 < M) ? *(const float4*)&A[(size_t)r1 * DIM + 16 + ac0] : z4;
    bv0 = *(const float4*)&B[(16 + br0) * DIM + bc0];
    bv1 = *(const float4*)&B[(16 + br1) * DIM + bc0];

    #pragma unroll 1
    for (int it = 0; it < 8; it++) {
        const int cur = it & 1;
        #pragma unroll
        for (int k = 0; k < 16; k++) {
            float a[8], b[8];
            *(float4*)(a)   = *(const float4*)&As[cur][k][ty*8];
            *(float4*)(a+4) = *(const float4*)&As[cur][k][ty*8+4];
            *(float4*)(b)   = *(const float4*)&Bs[cur][k][tx*8];
            *(float4*)(b+4) = *(const float4*)&Bs[cur][k][tx*8+4];
            #pragma unroll
            for (int i = 0; i < 8; i++)
                #pragma unroll
                for (int j = 0; j < 8; j++)
                    acc[i][j] = fmaf(a[i], b[j], acc[i][j]);
        }
        if (it < 7) {
            const int nxt = cur ^ 1;
            As[nxt][ac0+0][ar0] = av0.x; As[nxt][ac0+1][ar0] = av0.y; As[nxt][ac0+2][ar0] = av0.z; As[nxt][ac0+3][ar0] = av0.w;
            As[nxt][ac0+0][ar1] = av1.x; As[nxt][ac0+1][ar1] = av1.y; As[nxt][ac0+2][ar1] = av1.z; As[nxt][ac0+3][ar1] = av1.w;
            *(float4*)&Bs[nxt][br0][bc0] = bv0;
            *(float4*)&Bs[nxt][br1][bc0] = bv1;
            __syncthreads();
            if (it < 6) {
                int kk = (it + 2) * 16;
                av0 = (r0 < M) ? *(const float4*)&A[(size_t)r0 * DIM + kk + ac0] : z4;
                av1 = (r1 < M) ? *(const float4*)&A[(size_t)r1 * DIM + kk + ac0] : z4;
                bv0 = *(const float4*)&B[(kk + br0) * DIM + bc0];
                bv1 = *(const float4*)&B[(kk + br1) * DIM + bc0];
            }
        }
    }
}

// ================= HMMA BK=32 tile (round-11 proven; edge/plain kernels) =================
__device__ __forceinline__ void gemm_tile_hmma(
    const float* __restrict__ Asrc, int M, int row0, const uint32_t* __restrict__ wimg,
    uint32_t (*smA)[128 * RS2], uint32_t (*smB)[128 * RS2],
    float (&acc)[2][8][4])
{
    int tid = threadIdx.x, lid = tid & 31, wid = tid >> 5;
    int wm = wid & 3, wn = wid >> 2;
    int lrow = lid & 7, lj = lid >> 3;
    int a_row_off = ((lj & 1) << 3) + lrow;
    int a_word    = (lj >> 1) << 2;
    int b_row_off = ((lj >> 1) << 3) + lrow;
    int b_word    = (lj & 1) << 2;
    uint32_t sA0 = (uint32_t)__cvta_generic_to_shared(&smA[0][0]);
    uint32_t sA1 = (uint32_t)__cvta_generic_to_shared(&smA[1][0]);
    uint32_t sB0 = (uint32_t)__cvta_generic_to_shared(&smB[0][0]);
    uint32_t sB1 = (uint32_t)__cvta_generic_to_shared(&smB[1][0]);

    #pragma unroll 1
    for (int it = 0; it < 4; it++) {
        if (it) __syncthreads();
        #pragma unroll
        for (int q = 0; q < 8; q++) {
            int p = tid + q * 256;
            int row = p >> 4, kpl = p & 15;
            int r = row0 + row;
            float2 v = (r < M) ? *(const float2*)&Asrc[(size_t)r * DIM + it * 32 + kpl * 2]
                               : make_float2(0.f, 0.f);
            uint32_t hi, lo;
            split2(v.x, v.y, hi, lo);
            smA[0][row * RS2 + kpl] = hi;
            smA[1][row * RS2 + kpl] = lo;
        }
        #pragma unroll
        for (int q = 0; q < 8; q++) {
            int p = tid + q * 256;
            int n = p >> 4, kpl = p & 15;
            smB[0][n * RS2 + kpl] = wimg[n * 64 + it * 16 + kpl];
            smB[1][n * RS2 + kpl] = wimg[8192 + n * 64 + it * 16 + kpl];
        }
        __syncthreads();
        #pragma unroll
        for (int kk = 0; kk < 2; kk++) {
            uint32_t ah[2][4], al[2][4];
            #pragma unroll
            for (int mi = 0; mi < 2; mi++) {
                uint32_t off = (uint32_t)(((wm * 32 + mi * 16 + a_row_off) * RS2
                                           + kk * 8 + a_word) * 4);
                ldsm_x4(ah[mi], sA0 + off);
                ldsm_x4(al[mi], sA1 + off);
            }
            #pragma unroll
            for (int np = 0; np < 4; np++) {
                uint32_t off = (uint32_t)(((wn * 64 + np * 16 + b_row_off) * RS2
                                           + kk * 8 + b_word) * 4);
                uint32_t bh[4], bl[4];
                ldsm_x4(bh, sB0 + off);
                ldsm_x4(bl, sB1 + off);
                #pragma unroll
                for (int s = 0; s < 2; s++) {
                    int ni = np * 2 + s;
                    #pragma unroll
                    for (int mi = 0; mi < 2; mi++) {
                        mma16816(acc[mi][ni], ah[mi], bh[s*2], bh[s*2+1]);
                        mma16816(acc[mi][ni], ah[mi], bl[s*2], bl[s*2+1]);
                        mma16816(acc[mi][ni], al[mi], bh[s*2], bh[s*2+1]);
                    }
                }
            }
        }
    }
}

// ================= full-K A pieces (node kernel) =================
__device__ __forceinline__ void hmma_convert_A_full(
    const float* __restrict__ Asrc, int M, int row0, uint32_t* dsm)
{
    int tid = threadIdx.x;
    #pragma unroll
    for (int q = 0; q < 32; q++) {
        int p = tid + q * 256;
        int row = p >> 6, kw = p & 63;
        int r = row0 + row;
        float2 v = (r < M) ? *(const float2*)&Asrc[(size_t)r * DIM + kw * 2]
                           : make_float2(0.f, 0.f);
        uint32_t hi, lo;
        split2(v.x, v.y, hi, lo);
        dsm[row * RSA + kw] = hi;
        dsm[A_SPLIT_OFF + row * RSA + kw] = lo;
    }
}
__device__ __forceinline__ void hmma_copy_Bslice(
    const uint32_t* __restrict__ wimg, int it, uint32_t* dsm)
{
    int tid = threadIdx.x;
    #pragma unroll
    for (int q = 0; q < 8; q++) {
        int p = tid + q * 256;
        int n = p >> 4, kpl = p & 15;
        dsm[B_BASE + n * RS2 + kpl] = wimg[n * 64 + it * 16 + kpl];
        dsm[B_BASE + B_SPLIT_OFF + n * RS2 + kpl] = wimg[8192 + n * 64 + it * 16 + kpl];
    }
}
__device__ __forceinline__ void hmma_weight_loop(
    const uint32_t* __restrict__ wimg, uint32_t* dsm, float (&acc)[2][8][4])
{
    int tid = threadIdx.x, lid = tid & 31, wid = tid >> 5;
    int wm = wid & 3, wn = wid >> 2;
    int lrow = lid & 7, lj = lid >> 3;
    int a_row_off = ((lj & 1) << 3) + lrow;
    int a_word    = (lj >> 1) << 2;
    int b_row_off = ((lj >> 1) << 3) + lrow;
    int b_word    = (lj & 1) << 2;
    uint32_t sA0 = (uint32_t)__cvta_generic_to_shared(dsm);
    uint32_t sA1 = (uint32_t)__cvta_generic_to_shared(dsm + A_SPLIT_OFF);
    uint32_t sB0 = (uint32_t)__cvta_generic_to_shared(dsm + B_BASE);
    uint32_t sB1 = (uint32_t)__cvta_generic_to_shared(dsm + B_BASE + B_SPLIT_OFF);

    #pragma unroll 1
    for (int it = 0; it < 4; it++) {
        __syncthreads();
        hmma_copy_Bslice(wimg, it, dsm);
        __syncthreads();
        #pragma unroll
        for (int kk = 0; kk < 2; kk++) {
            uint32_t ah[2][4], al[2][4];
            #pragma unroll
            for (int mi = 0; mi < 2; mi++) {
                uint32_t off = (uint32_t)(((wm * 32 + mi * 16 + a_row_off) * RSA
                                           + it * 16 + kk * 8 + a_word) * 4);
                ldsm_x4(ah[mi], sA0 + off);
                ldsm_x4(al[mi], sA1 + off);
            }
            #pragma unroll
            for (int np = 0; np < 4; np++) {
                uint32_t off = (uint32_t)(((wn * 64 + np * 16 + b_row_off) * RS2
                                           + kk * 8 + b_word) * 4);
                uint32_t bh[4], bl[4];
                ldsm_x4(bh, sB0 + off);
                ldsm_x4(bl, sB1 + off);
                #pragma unroll
                for (int s = 0; s < 2; s++) {
                    int ni = np * 2 + s;
                    #pragma unroll
                    for (int mi = 0; mi < 2; mi++) {
                        mma16816(acc[mi][ni], ah[mi], bh[s*2], bh[s*2+1]);
                        mma16816(acc[mi][ni], ah[mi], bl[s*2], bl[s*2+1]);
                        mma16816(acc[mi][ni], al[mi], bh[s*2], bh[s*2+1]);
                    }
                }
            }
        }
    }
}

__device__ __forceinline__ void hmma_store(
    float (&acc)[2][8][4], int M, int row0, float* __restrict__ out, int ldc, int cbase,
    const float* __restrict__ s_bias)
{
    int tid = threadIdx.x, lid = tid & 31, wid = tid >> 5;
    int g = lid >> 2, t = lid & 3;
    int wm = wid & 3, wn = wid >> 2;
    #pragma unroll
    for (int mi = 0; mi < 2; mi++)
        #pragma unroll
        for (int hf = 0; hf < 2; hf++) {
            int r = row0 + wm * 32 + mi * 16 + hf * 8 + g;
            if (r < M) {
                #pragma unroll
                for (int ni = 0; ni < 8; ni++) {
                    int c = wn * 64 + ni * 8 + t * 2;
                    *(float2*)&out[(size_t)r * ldc + cbase + c] = make_float2(
                        acc[mi][ni][hf * 2 + 0] + s_bias[c],
                        acc[mi][ni][hf * 2 + 1] + s_bias[c + 1]);
                }
            }
        }
}

// ---------------- unified GEMM (embeddings; round-11 static smem) ----------------
__global__ void __launch_bounds__(256, 2) k_gemm_plain(
    const float* __restrict__ A, const float* __restrict__ W, int widx,
    const float* __restrict__ bias, int M, int which)
{
    __shared__ __align__(16) uint32_t smraw[UNION_U32];
    __shared__ float s_bias[DIM];
    int tid = threadIdx.x;
    int row0 = blockIdx.x * 128;
    float* out = which ? g_e : g_h;
    if (tid < DIM) s_bias[tid] = bias[tid];
    __syncthreads();

    if (g_hmma_ok) {
        uint32_t (*hA)[128 * RS2] = reinterpret_cast<uint32_t(*)[128 * RS2]>(smraw);
        uint32_t (*hB)[128 * RS2] = reinterpret_cast<uint32_t(*)[128 * RS2]>(smraw + 2 * 128 * RS2);
        float acc[2][8][4] = {};
        gemm_tile_hmma(A, M, row0, &g_wimg[(size_t)widx * IMG_U32], hA, hB, acc);
        hmma_store(acc, M, row0, out, DIM, 0, s_bias);
    } else {
        float (*As)[16][DIM] = reinterpret_cast<float(*)[16][DIM]>(smraw);
        float (*Bs)[16][DIM] = reinterpret_cast<float(*)[16][DIM]>(smraw + 4096);
        float acc[8][8] = {};
        gemm_mainloop(A, W, M, row0, acc, As, Bs);
        int tx = tid & 15, ty = tid >> 4;
        int c0 = tx * 8;
        #pragma unroll
        for (int i = 0; i < 8; i++) {
            int r = row0 + ty*8 + i;
            if (r < M) {
                #pragma unroll
                for (int j = 0; j < 8; j++)
                    out[(size_t)r * DIM + c0 + j] = acc[i][j] + s_bias[c0 + j];
            }
        }
    }
}

// ---------------- node GEMM: grid (157,2); y=0 -> A,B; y=1 -> D,E (A converted once per pair) ----------------
__global__ void __launch_bounds__(256, 2) k_gemm_node2(
    int l, const float* __restrict__ Aw, const float* __restrict__ Bw,
    const float* __restrict__ Dw, const float* __restrict__ Ew,
    const float* __restrict__ Ab, const float* __restrict__ Bb,
    const float* __restrict__ Db, const float* __restrict__ Eb)
{
    extern __shared__ uint32_t dsm[];
    __shared__ float s_bias[2 * DIM];
    int tid = threadIdx.x;
    int row0 = blockIdx.x * 128;
    int y = blockIdx.y;                 // 0 -> (A,B), 1 -> (D,E)
    int base = 2 + l * 5;
    int w0 = (y == 0) ? base + 0 : base + 3;
    int w1 = (y == 0) ? base + 1 : base + 4;
    const float* b0 = (y == 0) ? Ab : Db;
    const float* b1 = (y == 0) ? Bb : Eb;
    int cb0 = (y == 0) ? 0 : 2 * DIM;   // output col base in g_abde

    if (tid < DIM) { s_bias[tid] = b0[tid]; s_bias[DIM + tid] = b1[tid]; }

    if (g_hmma_ok) {
        hmma_convert_A_full(g_h, N_NODES, row0, dsm);
        {
            float acc[2][8][4] = {};
            hmma_weight_loop(&g_wimg[(size_t)w0 * IMG_U32], dsm, acc);
            hmma_store(acc, N_NODES, row0, g_abde, 512, cb0, &s_bias[0]);
        }
        {
            float acc[2][8][4] = {};
            hmma_weight_loop(&g_wimg[(size_t)w1 * IMG_U32], dsm, acc);
            hmma_store(acc, N_NODES, row0, g_abde, 512, cb0 + DIM, &s_bias[DIM]);
        }
    } else {
        float (*As)[16][DIM] = reinterpret_cast<float(*)[16][DIM]>(dsm);
        float (*Bs)[16][DIM] = reinterpret_cast<float(*)[16][DIM]>(dsm + 4096);
        int tx = tid & 15, ty = tid >> 4;
        int c0 = tx * 8;
        for (int s = 0; s < 2; s++) {
            const float* W = (y == 0) ? (s == 0 ? Aw : Bw) : (s == 0 ? Dw : Ew);
            float acc[8][8] = {};
            __syncthreads();
            gemm_mainloop(g_h, W, N_NODES, row0, acc, As, Bs);
            #pragma unroll
            for (int i = 0; i < 8; i++) {
                int r = row0 + ty*8 + i;
                if (r < N_NODES) {
                    #pragma unroll
                    for (int j = 0; j < 8; j++)
                        g_abde[(size_t)r * 512 + cb0 + s * DIM + c0 + j]
                            = acc[i][j] + s_bias[s * DIM + c0 + j];
                }
            }
            __syncthreads();
        }
    }
}

// ---------------- edge GEMM + gather + (optional) e-BN stats (round-11 static smem) ----------------
__global__ void __launch_bounds__(256, 2) k_gemm_edge(
    int l, const float* __restrict__ Cw, const float* __restrict__ Cb,
    const int* __restrict__ src, const int* __restrict__ dst, int do_estats)
{
    __shared__ __align__(16) uint32_t smraw[UNION_U32];
    __shared__ float s_cb[DIM], s_sum[DIM], s_sq[DIM];
    int tid = threadIdx.x, lid = tid & 31, wid = tid >> 5;
    int row0 = blockIdx.x * 128;
    if (tid < DIM) { s_cb[tid] = Cb[tid]; s_sum[tid] = 0.f; s_sq[tid] = 0.f; }
    __syncthreads();

    if (g_hmma_ok) {
        uint32_t (*hA)[128 * RS2] = reinterpret_cast<uint32_t(*)[128 * RS2]>(smraw);
        uint32_t (*hB)[128 * RS2] = reinterpret_cast<uint32_t(*)[128 * RS2]>(smraw + 2 * 128 * RS2);
        int g = lid >> 2, t = lid & 3;
        int wm = wid & 3, wn = wid >> 2;
        float acc[2][8][4] = {};
        gemm_tile_hmma(g_e, N_EDGES, row0, &g_wimg[(size_t)(2 + l * 5 + 2) * IMG_U32], hA, hB, acc);

        int rows[4], svr[4], dvr[4];
        #pragma unroll
        for (int ridx = 0; ridx < 4; ridx++) {
            int mi = ridx >> 1, hf = ridx & 1;
            rows[ridx] = row0 + wm * 32 + mi * 16 + hf * 8 + g;
            svr[ridx] = src[rows[ridx]];
            dvr[ridx] = dst[rows[ridx]];
        }
        #pragma unroll
        for (int ni = 0; ni < 8; ni++) {
            int c = wn * 64 + ni * 8 + t * 2;
            float cb0 = s_cb[c], cb1 = s_cb[c + 1];
            float s0 = 0.f, s1 = 0.f, q0 = 0.f, q1 = 0.f;
            #pragma unroll
            for (int ridx = 0; ridx < 4; ridx++) {
                int mi = ridx >> 1, hf = ridx & 1;
                float2 dD = *(const float2*)&g_abde[(size_t)svr[ridx] * 512 + 256 + c];
                float2 dE = *(const float2*)&g_abde[(size_t)dvr[ridx] * 512 + 384 + c];
                float v0 = acc[mi][ni][hf * 2 + 0] + cb0 + dD.x + dE.x;
                float v1 = acc[mi][ni][hf * 2 + 1] + cb1 + dD.y + dE.y;
                *(float2*)&g_enew[(size_t)rows[ridx] * DIM + c] = make_float2(v0, v1);
                s0 += v0; q0 += v0 * v0;
                s1 += v1; q1 += v1 * v1;
            }
            if (do_estats) {
                #pragma unroll
                for (int s = 4; s < 32; s <<= 1) {
                    s0 += __shfl_xor_sync(0xffffffffu, s0, s);
                    s1 += __shfl_xor_sync(0xffffffffu, s1, s);
                    q0 += __shfl_xor_sync(0xffffffffu, q0, s);
                    q1 += __shfl_xor_sync(0xffffffffu, q1, s);
                }
                if (g == 0) {
                    atomicAdd(&s_sum[c], s0);     atomicAdd(&s_sq[c], q0);
                    atomicAdd(&s_sum[c + 1], s1); atomicAdd(&s_sq[c + 1], q1);
                }
            }
        }
    } else {
        float (*As)[16][DIM] = reinterpret_cast<float(*)[16][DIM]>(smraw);
        float (*Bs)[16][DIM] = reinterpret_cast<float(*)[16][DIM]>(smraw + 4096);
        float acc[8][8] = {};
        gemm_mainloop(g_e, Cw, N_EDGES, row0, acc, As, Bs);
        __syncthreads();
        int tx = tid & 15, ty = tid >> 4;
        int c0 = tx * 8;
        float cb[8];
        #pragma unroll
        for (int j = 0; j < 8; j++) cb[j] = s_cb[c0 + j];
        float csum[8] = {}, csq[8] = {};
        #pragma unroll 1
        for (int i = 0; i < 8; i++) {
            int r = row0 + ty*8 + i;
            int sv = src[r], dv = dst[r];
            const float* Dp = &g_abde[(size_t)sv * 512 + 256 + c0];
            const float* Ep = &g_abde[(size_t)dv * 512 + 384 + c0];
            float dh[8], eh[8], ev[8];
            *(float4*)(dh)   = *(const float4*)(Dp);
            *(float4*)(dh+4) = *(const float4*)(Dp+4);
            *(float4*)(eh)   = *(const float4*)(Ep);
            *(float4*)(eh+4) = *(const float4*)(Ep+4);
            #pragma unroll
            for (int j = 0; j < 8; j++) {
                float v = acc[i][j] + cb[j] + dh[j] + eh[j];
                ev[j] = v;
                csum[j] += v;
                csq[j]  += v * v;
            }
            *(float4*)&g_enew[(size_t)r * DIM + c0]     = *(float4*)(ev);
            *(float4*)&g_enew[(size_t)r * DIM + c0 + 4] = *(float4*)(ev+4);
        }
        if (do_estats) {
            #pragma unroll
            for (int j = 0; j < 8; j++) {
                atomicAdd(&s_sum[c0 + j], csum[j]);
                atomicAdd(&s_sq[c0 + j],  csq[j]);
            }
        }
    }
    __syncthreads();
    if (do_estats && tid < DIM) {
        atomicAdd(&g_stats[2*DIM + tid], (double)s_sum[tid]);
        atomicAdd(&g_stats[3*DIM + tid], (double)s_sq[tid]);
    }
}

// ================= CSR build =================
__global__ void k_zero_cnt() {
    int i = blockIdx.x * blockDim.x + threadIdx.x;
    if (i < N_NODES) { g_cnt[i] = 0; g_cnt2[i] = 0; }
}
__global__ void k_hist(const int* __restrict__ dst) {
    int e = blockIdx.x * blockDim.x + threadIdx.x;
    if (e < N_EDGES) atomicAdd(&g_cnt[dst[e]], 1);
}
__global__ void k_scan() {
    __shared__ int s[1024];
    int tn = threadIdx.x;
    int base = tn * 20;
    int loc[20];
    int sum = 0;
    #pragma unroll
    for (int j = 0; j < 20; j++) {
        int idx = base + j;
        loc[j] = sum;
        if (idx < N_NODES) sum += g_cnt[idx];
    }
    s[tn] = sum;
    __syncthreads();
    for (int off = 1; off < 1024; off <<= 1) {
        int v = (tn >= off) ? s[tn - off] : 0;
        __syncthreads();
        s[tn] += v;
        __syncthreads();
    }
    int pre = (tn > 0) ? s[tn - 1] : 0;
    #pragma unroll
    for (int j = 0; j < 20; j++) {
        int idx = base + j;
        if (idx < N_NODES) g_csr[idx] = pre + loc[j];
    }
    if (tn == 1023) g_csr[N_NODES] = s[1023];
}
__global__ void k_scatter(const int* __restrict__ src, const int* __restrict__ dst) {
    int e = blockIdx.x * blockDim.x + threadIdx.x;
    if (e < N_EDGES) {
        int d = dst[e];
        int pos = g_csr[d] + atomicAdd(&g_cnt2[d], 1);
        g_perm[pos] = e;
        g_srcp[pos] = src[e];
    }
}
__global__ void k_zero_stats() {
    int i = threadIdx.x;
    if (i < 4 * DIM) g_stats[i] = 0.0;
}

// ---------------- per-node aggregation ----------------
__global__ void __launch_bounds__(128) k_aggregate() {
    int n = blockIdx.x;
    int t = threadIdx.x;
    int beg = g_csr[n], end = g_csr[n + 1];
    float num = 0.f, den = 0.f;
    for (int i = beg; i < end; i++) {
        int e = g_perm[i];
        int s = g_srcp[i];
        float v = g_enew[(size_t)e * DIM + t];
        float bh = g_abde[(size_t)s * 512 + 128 + t];
        float sg = 1.f / (1.f + __expf(-v));
        num = fmaf(sg, bh, num);
        den += sg;
    }
    float hv = g_abde[(size_t)n * 512 + t] + num / (den + 1e-6f);
    g_hnew[n * DIM + t] = hv;
}

__global__ void __launch_bounds__(256) k_hstats() {
    __shared__ float s_sum[DIM];
    __shared__ float s_sq[DIM];
    int tid = threadIdx.x;
    if (tid < DIM) { s_sum[tid] = 0.f; s_sq[tid] = 0.f; }
    __syncthreads();
    int col = tid & 127;
    int rh = tid >> 7;
    int row0 = blockIdx.x * 128;
    float ls = 0.f, lq = 0.f;
    for (int i = rh; i < 128; i += 2) {
        int r = row0 + i;
        if (r < N_NODES) {
            float v = g_hnew[r * DIM + col];
            ls += v; lq += v * v;
        }
    }
    atomicAdd(&s_sum[col], ls);
    atomicAdd(&s_sq[col], lq);
    __syncthreads();
    if (tid < DIM) {
        atomicAdd(&g_stats[tid],       (double)s_sum[tid]);
        atomicAdd(&g_stats[DIM + tid], (double)s_sq[tid]);
    }
}

// finalize both BN param sets (e optional) and reset stats for next layer
__global__ void k_finalize(const float* __restrict__ gh, const float* __restrict__ bh,
                           const float* __restrict__ ge, const float* __restrict__ be,
                           int do_e)
{
    int t = threadIdx.x;
    if (t < DIM) {
        double mu  = g_stats[t] / (double)N_NODES;
        double var = g_stats[DIM + t] / (double)N_NODES - mu * mu;
        double rstd = 1.0 / sqrt(var + 1e-5);
        float sc = gh[t] * (float)rstd;
        g_bn[t] = sc;
        g_bn[DIM + t] = bh[t] - (float)mu * sc;
    } else if (t < 2 * DIM && do_e) {
        int c = t - DIM;
        double mu  = g_stats[2*DIM + c] / (double)N_EDGES;
        double var = g_stats[3*DIM + c] / (double)N_EDGES - mu * mu;
        double rstd = 1.0 / sqrt(var + 1e-5);
        float sc = ge[c] * (float)rstd;
        g_bn[2*DIM + c] = sc;
        g_bn[3*DIM + c] = be[c] - (float)mu * sc;
    }
    __syncthreads();
    g_stats[t] = 0.0;
    g_stats[t + 256] = 0.0;
}

__global__ void k_apply_h() {
    int i4 = blockIdx.x * blockDim.x + threadIdx.x;
    if (i4 < N_NODES * DIM / 4) {
        int c4 = (i4 & 31) * 4;
        float4 v  = *(const float4*)&g_hnew[i4 * 4];
        float4 sc = *(const float4*)&g_bn[c4];
        float4 sh = *(const float4*)&g_bn[DIM + c4];
        float4 hv = *(const float4*)&g_h[i4 * 4];
        hv.x += fmaxf(fmaf(v.x, sc.x, sh.x), 0.f);
        hv.y += fmaxf(fmaf(v.y, sc.y, sh.y), 0.f);
        hv.z += fmaxf(fmaf(v.z, sc.z, sh.z), 0.f);
        hv.w += fmaxf(fmaf(v.w, sc.w, sh.w), 0.f);
        *(float4*)&g_h[i4 * 4] = hv;
    }
}
__global__ void k_apply_e() {
    int i4 = blockIdx.x * blockDim.x + threadIdx.x;
    if (i4 < N_EDGES * DIM / 4) {
        int c4 = (i4 & 31) * 4;
        float4 v  = *(const float4*)&g_enew[(size_t)i4 * 4];
        float4 sc = *(const float4*)&g_bn[2*DIM + c4];
        float4 sh = *(const float4*)&g_bn[3*DIM + c4];
        float4 evv = *(const float4*)&g_e[(size_t)i4 * 4];
        evv.x += fmaxf(fmaf(v.x, sc.x, sh.x), 0.f);
        evv.y += fmaxf(fmaf(v.y, sc.y, sh.y), 0.f);
        evv.z += fmaxf(fmaf(v.z, sc.z, sh.z), 0.f);
        evv.w += fmaxf(fmaf(v.w, sc.w, sh.w), 0.f);
        *(float4*)&g_e[(size_t)i4 * 4] = evv;
    }
}

// ---------------- host launch ----------------
extern "C" void kernel_launch(void* const* d_in, const int* in_sizes, int n_in,
                              void* d_out, int out_size)
{
    const float* h0  = (const float*)d_in[0];
    const float* e0  = (const float*)d_in[1];
    const int*   src = (const int*)  d_in[2];
    const int*   dst = (const int*)  d_in[3];
    const float* Wh  = (const float*)d_in[4];
    const float* bhe = (const float*)d_in[5];
    const float* We  = (const float*)d_in[6];
    const float* bee = (const float*)d_in[7];
    const float* Aw  = (const float*)d_in[8];
    const float* Ab  = (const float*)d_in[9];
    const float* Bw  = (const float*)d_in[10];
    const float* Bb  = (const float*)d_in[11];
    const float* Cw  = (const float*)d_in[12];
    const float* Cb  = (const float*)d_in[13];
    const float* Dw  = (const float*)d_in[14];
    const float* Db  = (const float*)d_in[15];
    const float* Ew  = (const float*)d_in[16];
    const float* Eb  = (const float*)d_in[17];
    const float* gh  = (const float*)d_in[18];
    const float* bh  = (const float*)d_in[19];
    const float* ge  = (const float*)d_in[20];
    const float* be  = (const float*)d_in[21];

    const int grid_node = (N_NODES + 127) / 128;   // 157
    const int grid_edge = N_EDGES / 128;           // 2000

    cudaFuncSetAttribute(k_gemm_node2, cudaFuncAttributeMaxDynamicSharedMemorySize, DYN_BYTES);

    // launch #4 = edge-embedding HMMA GEMM -> the kernel ncu displays
    k_probe<<<1, 32>>>();
    k_prep_w<<<22, 256>>>(Wh, We, Aw, Bw, Cw, Dw, Ew);
    k_gemm_plain<<<grid_node, 256>>>(h0, Wh, 0, bhe, N_NODES, 0);
    k_gemm_plain<<<grid_edge, 256>>>(e0, We, 1, bee, N_EDGES, 1);

    k_zero_cnt<<<(N_NODES + 255) / 256, 256>>>();
    k_hist<<<(N_EDGES + 255) / 256, 256>>>(dst);
    k_scan<<<1, 1024>>>();
    k_scatter<<<(N_EDGES + 255) / 256, 256>>>(src, dst);
    k_zero_stats<<<1, 512>>>();

    for (int l = 0; l < 4; l++) {
        int do_e = (l < 3) ? 1 : 0;   // e_3 dead: no stats/finalize/apply
        k_gemm_node2<<<dim3(grid_node, 2), 256, DYN_BYTES>>>(l,
            Aw + l*DD, Bw + l*DD, Dw + l*DD, Ew + l*DD,
            Ab + l*DIM, Bb + l*DIM, Db + l*DIM, Eb + l*DIM);
        k_gemm_edge<<<grid_edge, 256>>>(l, Cw + l*DD, Cb + l*DIM, src, dst, do_e);
        k_aggregate<<<N_NODES, 128>>>();
        k_hstats<<<grid_node, 256>>>();
        k_finalize<<<1, 256>>>(gh + l*DIM, bh + l*DIM, ge + l*DIM, be + l*DIM, do_e);
        k_apply_h<<<(N_NODES * DIM / 4 + 255) / 256, 256>>>();
        if (do_e)
            k_apply_e<<<(N_EDGES * DIM / 4 + 255) / 256, 256>>>();
    }

    cudaMemcpyFromSymbolAsync(d_out, g_h, sizeof(float) * N_NODES * DIM, 0,
                              cudaMemcpyDeviceToDevice, 0);
}

// round 15
// speedup vs baseline: 1.0443x; 1.0086x over previous
#include <cuda_runtime.h>
#include <cstdint>

#define N_NODES 20000
#define N_EDGES 256000
#define DIM 128
#define DD (DIM*DIM)

#define RS2 20                       // BK=32 smem row stride (u32)
#define RSA 68                       // full-K A smem row stride (u32)
#define IMG_U32 16384                // per-matrix bf16 image (8192 hi + 8192 lo)
#define UNION_U32 10240              // 40KB static smem union (edge/plain kernels)
#define A_SPLIT_OFF (128 * RSA)
#define B_BASE      (2 * 128 * RSA)
#define B_SPLIT_OFF (128 * RS2)
#define DYN_U32   (B_BASE + 2 * B_SPLIT_OFF)
#define DYN_BYTES (DYN_U32 * 4)      // 90112 B (node kernel only)

// ---------------- static device scratch ----------------
__device__ float  g_h   [N_NODES * DIM];
__device__ float  g_e   [N_EDGES * DIM];
__device__ float  g_abde[N_NODES * 4 * DIM];
__device__ float  g_enew[N_EDGES * DIM];
__device__ float  g_hnew[N_NODES * DIM];
__device__ double g_stats[4 * DIM];
__device__ float  g_bn  [4 * DIM];
__device__ int    g_cnt [N_NODES];
__device__ int    g_cnt2[N_NODES];
__device__ int    g_csr [N_NODES + 1];
__device__ int    g_perm[N_EDGES];
__device__ int    g_srcp[N_EDGES];
__device__ uint32_t g_wimg[22 * IMG_U32];
__device__ int    g_hmma_ok;

// ---------------- bf16 helpers ----------------
__device__ __forceinline__ uint32_t pack2(float a, float b) {
    uint32_t r; asm("cvt.rn.bf16x2.f32 %0, %1, %2;" : "=r"(r) : "f"(b), "f"(a)); return r;
}
__device__ __forceinline__ void split2(float a, float b, uint32_t& hi, uint32_t& lo) {
    hi = pack2(a, b);
    float ha = __uint_as_float(hi << 16);
    float hb = __uint_as_float(hi & 0xffff0000u);
    lo = pack2(a - ha, b - hb);
}
__device__ __forceinline__ void mma16816(float (&d)[4], const uint32_t (&a)[4],
                                         const uint32_t b0, const uint32_t b1) {
    asm volatile("mma.sync.aligned.m16n8k16.row.col.f32.bf16.bf16.f32 "
        "{%0,%1,%2,%3}, {%4,%5,%6,%7}, {%8,%9}, {%0,%1,%2,%3};"
        : "+f"(d[0]), "+f"(d[1]), "+f"(d[2]), "+f"(d[3])
        : "r"(a[0]), "r"(a[1]), "r"(a[2]), "r"(a[3]), "r"(b0), "r"(b1));
}
__device__ __forceinline__ void ldsm_x4(uint32_t (&r)[4], uint32_t saddr) {
    asm volatile("ldmatrix.sync.aligned.m8n8.x4.shared.b16 {%0,%1,%2,%3}, [%4];"
        : "=r"(r[0]), "=r"(r[1]), "=r"(r[2]), "=r"(r[3]) : "r"(saddr));
}

// ================= numeric HMMA probe =================
__global__ void k_probe() {
    uint32_t one2 = 0x3f803f80u;
    uint32_t a[4] = {one2, one2, one2, one2};
    float d[4] = {0.f, 0.f, 0.f, 0.f};
    mma16816(d, a, one2, one2);
    bool ok = (d[0] == 16.f) && (d[1] == 16.f) && (d[2] == 16.f) && (d[3] == 16.f);
    unsigned m = __ballot_sync(0xffffffffu, ok);
    if ((threadIdx.x & 31) == 0) g_hmma_ok = (m == 0xffffffffu) ? 1 : 0;
}

// ---------------- weight prep ----------------
__global__ void k_prep_w(const float* Wh, const float* We,
                         const float* Aw, const float* Bw, const float* Cw,
                         const float* Dw, const float* Ew)
{
    int bx = blockIdx.x;
    const float* W;
    if (bx == 0) W = Wh;
    else if (bx == 1) W = We;
    else {
        int i = bx - 2, l = i / 5, w = i % 5;
        W = ((w == 0) ? Aw : (w == 1) ? Bw : (w == 2) ? Cw : (w == 3) ? Dw : Ew) + (size_t)l * DD;
    }
    uint32_t* img = &g_wimg[(size_t)bx * IMG_U32];
    for (int p = threadIdx.x; p < 8192; p += blockDim.x) {
        int n = p >> 6, kp = p & 63, k = kp << 1;
        uint32_t hi, lo;
        split2(W[k * DIM + n], W[(k + 1) * DIM + n], hi, lo);
        img[n * 64 + kp] = hi;
        img[8192 + n * 64 + kp] = lo;
    }
}

// ================= SIMT fp32 mainloop (fallback) =================
__device__ __forceinline__ void gemm_mainloop(
    const float* __restrict__ A, const float* __restrict__ B,
    int M, int row0, float (&acc)[8][8],
    float (*As)[16][DIM], float (*Bs)[16][DIM])
{
    const int tid = threadIdx.x;
    const int ty = tid >> 4, tx = tid & 15;
    const int ar0 = tid >> 2, ac0 = (tid & 3) << 2;
    const int ar1 = ar0 + 64;
    const int br0 = tid >> 5, bc0 = (tid & 31) << 2;
    const int br1 = br0 + 8;
    const int r0 = row0 + ar0, r1 = row0 + ar1;
    const float4 z4 = make_float4(0.f, 0.f, 0.f, 0.f);
    float4 av0, av1, bv0, bv1;

    av0 = (r0 < M) ? *(const float4*)&A[(size_t)r0 * DIM + ac0] : z4;
    av1 = (r1 < M) ? *(const float4*)&A[(size_t)r1 * DIM + ac0] : z4;
    bv0 = *(const float4*)&B[br0 * DIM + bc0];
    bv1 = *(const float4*)&B[br1 * DIM + bc0];
    As[0][ac0+0][ar0] = av0.x; As[0][ac0+1][ar0] = av0.y; As[0][ac0+2][ar0] = av0.z; As[0][ac0+3][ar0] = av0.w;
    As[0][ac0+0][ar1] = av1.x; As[0][ac0+1][ar1] = av1.y; As[0][ac0+2][ar1] = av1.z; As[0][ac0+3][ar1] = av1.w;
    *(float4*)&Bs[0][br0][bc0] = bv0;
    *(float4*)&Bs[0][br1][bc0] = bv1;
    __syncthreads();

    av0 = (r0 < M) ? *(const float4*)&A[(size_t)r0 * DIM + 16 + ac0] : z4;
    av1 = (r1 < M) ? *(const float4*)&A[(size_t)r1 * DIM + 16 + ac0] : z4;
    bv0 = *(const float4*)&B[(16 + br0) * DIM + bc0];
    bv1 = *(const float4*)&B[(16 + br1) * DIM + bc0];

    #pragma unroll 1
    for (int it = 0; it < 8; it++) {
        const int cur = it & 1;
        #pragma unroll
        for (int k = 0; k < 16; k++) {
            float a[8], b[8];
            *(float4*)(a)   = *(const float4*)&As[cur][k][ty*8];
            *(float4*)(a+4) = *(const float4*)&As[cur][k][ty*8+4];
            *(float4*)(b)   = *(const float4*)&Bs[cur][k][tx*8];
            *(float4*)(b+4) = *(const float4*)&Bs[cur][k][tx*8+4];
            #pragma unroll
            for (int i = 0; i < 8; i++)
                #pragma unroll
                for (int j = 0; j < 8; j++)
                    acc[i][j] = fmaf(a[i], b[j], acc[i][j]);
        }
        if (it < 7) {
            const int nxt = cur ^ 1;
            As[nxt][ac0+0][ar0] = av0.x; As[nxt][ac0+1][ar0] = av0.y; As[nxt][ac0+2][ar0] = av0.z; As[nxt][ac0+3][ar0] = av0.w;
            As[nxt][ac0+0][ar1] = av1.x; As[nxt][ac0+1][ar1] = av1.y; As[nxt][ac0+2][ar1] = av1.z; As[nxt][ac0+3][ar1] = av1.w;
            *(float4*)&Bs[nxt][br0][bc0] = bv0;
            *(float4*)&Bs[nxt][br1][bc0] = bv1;
            __syncthreads();
            if (it < 6) {
                int kk = (it + 2) * 16;
                av0 = (r0 < M) ? *(const float4*)&A[(size_t)r0 * DIM + kk + ac0] : z4;
                av1 = (r1 < M) ? *(const float4*)&A[(size_t)r1 * DIM + kk + ac0] : z4;
                bv0 = *(const float4*)&B[(kk + br0) * DIM + bc0];
                bv1 = *(const float4*)&B[(kk + br1) * DIM + bc0];
            }
        }
    }
}

// ================= HMMA BK=32 tile (edge/plain kernels) =================
__device__ __forceinline__ void gemm_tile_hmma(
    const float* __restrict__ Asrc, int M, int row0, const uint32_t* __restrict__ wimg,
    uint32_t (*smA)[128 * RS2], uint32_t (*smB)[128 * RS2],
    float (&acc)[2][8][4])
{
    int tid = threadIdx.x, lid = tid & 31, wid = tid >> 5;
    int wm = wid & 3, wn = wid >> 2;
    int lrow = lid & 7, lj = lid >> 3;
    int a_row_off = ((lj & 1) << 3) + lrow;
    int a_word    = (lj >> 1) << 2;
    int b_row_off = ((lj >> 1) << 3) + lrow;
    int b_word    = (lj & 1) << 2;
    uint32_t sA0 = (uint32_t)__cvta_generic_to_shared(&smA[0][0]);
    uint32_t sA1 = (uint32_t)__cvta_generic_to_shared(&smA[1][0]);
    uint32_t sB0 = (uint32_t)__cvta_generic_to_shared(&smB[0][0]);
    uint32_t sB1 = (uint32_t)__cvta_generic_to_shared(&smB[1][0]);

    #pragma unroll 1
    for (int it = 0; it < 4; it++) {
        if (it) __syncthreads();
        #pragma unroll
        for (int q = 0; q < 8; q++) {
            int p = tid + q * 256;
            int row = p >> 4, kpl = p & 15;
            int r = row0 + row;
            float2 v = (r < M) ? *(const float2*)&Asrc[(size_t)r * DIM + it * 32 + kpl * 2]
                               : make_float2(0.f, 0.f);
            uint32_t hi, lo;
            split2(v.x, v.y, hi, lo);
            smA[0][row * RS2 + kpl] = hi;
            smA[1][row * RS2 + kpl] = lo;
        }
        #pragma unroll
        for (int q = 0; q < 8; q++) {
            int p = tid + q * 256;
            int n = p >> 4, kpl = p & 15;
            smB[0][n * RS2 + kpl] = wimg[n * 64 + it * 16 + kpl];
            smB[1][n * RS2 + kpl] = wimg[8192 + n * 64 + it * 16 + kpl];
        }
        __syncthreads();
        #pragma unroll
        for (int kk = 0; kk < 2; kk++) {
            uint32_t ah[2][4], al[2][4];
            #pragma unroll
            for (int mi = 0; mi < 2; mi++) {
                uint32_t off = (uint32_t)(((wm * 32 + mi * 16 + a_row_off) * RS2
                                           + kk * 8 + a_word) * 4);
                ldsm_x4(ah[mi], sA0 + off);
                ldsm_x4(al[mi], sA1 + off);
            }
            #pragma unroll
            for (int np = 0; np < 4; np++) {
                uint32_t off = (uint32_t)(((wn * 64 + np * 16 + b_row_off) * RS2
                                           + kk * 8 + b_word) * 4);
                uint32_t bh[4], bl[4];
                ldsm_x4(bh, sB0 + off);
                ldsm_x4(bl, sB1 + off);
                #pragma unroll
                for (int s = 0; s < 2; s++) {
                    int ni = np * 2 + s;
                    #pragma unroll
                    for (int mi = 0; mi < 2; mi++) {
                        mma16816(acc[mi][ni], ah[mi], bh[s*2], bh[s*2+1]);
                        mma16816(acc[mi][ni], ah[mi], bl[s*2], bl[s*2+1]);
                        mma16816(acc[mi][ni], al[mi], bh[s*2], bh[s*2+1]);
                    }
                }
            }
        }
    }
}

// ================= full-K A pieces (node kernel) =================
__device__ __forceinline__ void hmma_convert_A_full(
    const float* __restrict__ Asrc, int M, int row0, uint32_t* dsm)
{
    int tid = threadIdx.x;
    #pragma unroll
    for (int q = 0; q < 32; q++) {
        int p = tid + q * 256;
        int row = p >> 6, kw = p & 63;
        int r = row0 + row;
        float2 v = (r < M) ? *(const float2*)&Asrc[(size_t)r * DIM + kw * 2]
                           : make_float2(0.f, 0.f);
        uint32_t hi, lo;
        split2(v.x, v.y, hi, lo);
        dsm[row * RSA + kw] = hi;
        dsm[A_SPLIT_OFF + row * RSA + kw] = lo;
    }
}
__device__ __forceinline__ void hmma_copy_Bslice(
    const uint32_t* __restrict__ wimg, int it, uint32_t* dsm)
{
    int tid = threadIdx.x;
    #pragma unroll
    for (int q = 0; q < 8; q++) {
        int p = tid + q * 256;
        int n = p >> 4, kpl = p & 15;
        dsm[B_BASE + n * RS2 + kpl] = wimg[n * 64 + it * 16 + kpl];
        dsm[B_BASE + B_SPLIT_OFF + n * RS2 + kpl] = wimg[8192 + n * 64 + it * 16 + kpl];
    }
}
__device__ __forceinline__ void hmma_weight_loop(
    const uint32_t* __restrict__ wimg, uint32_t* dsm, float (&acc)[2][8][4])
{
    int tid = threadIdx.x, lid = tid & 31, wid = tid >> 5;
    int wm = wid & 3, wn = wid >> 2;
    int lrow = lid & 7, lj = lid >> 3;
    int a_row_off = ((lj & 1) << 3) + lrow;
    int a_word    = (lj >> 1) << 2;
    int b_row_off = ((lj >> 1) << 3) + lrow;
    int b_word    = (lj & 1) << 2;
    uint32_t sA0 = (uint32_t)__cvta_generic_to_shared(dsm);
    uint32_t sA1 = (uint32_t)__cvta_generic_to_shared(dsm + A_SPLIT_OFF);
    uint32_t sB0 = (uint32_t)__cvta_generic_to_shared(dsm + B_BASE);
    uint32_t sB1 = (uint32_t)__cvta_generic_to_shared(dsm + B_BASE + B_SPLIT_OFF);

    #pragma unroll 1
    for (int it = 0; it < 4; it++) {
        __syncthreads();
        hmma_copy_Bslice(wimg, it, dsm);
        __syncthreads();
        #pragma unroll
        for (int kk = 0; kk < 2; kk++) {
            uint32_t ah[2][4], al[2][4];
            #pragma unroll
            for (int mi = 0; mi < 2; mi++) {
                uint32_t off = (uint32_t)(((wm * 32 + mi * 16 + a_row_off) * RSA
                                           + it * 16 + kk * 8 + a_word) * 4);
                ldsm_x4(ah[mi], sA0 + off);
                ldsm_x4(al[mi], sA1 + off);
            }
            #pragma unroll
            for (int np = 0; np < 4; np++) {
                uint32_t off = (uint32_t)(((wn * 64 + np * 16 + b_row_off) * RS2
                                           + kk * 8 + b_word) * 4);
                uint32_t bh[4], bl[4];
                ldsm_x4(bh, sB0 + off);
                ldsm_x4(bl, sB1 + off);
                #pragma unroll
                for (int s = 0; s < 2; s++) {
                    int ni = np * 2 + s;
                    #pragma unroll
                    for (int mi = 0; mi < 2; mi++) {
                        mma16816(acc[mi][ni], ah[mi], bh[s*2], bh[s*2+1]);
                        mma16816(acc[mi][ni], ah[mi], bl[s*2], bl[s*2+1]);
                        mma16816(acc[mi][ni], al[mi], bh[s*2], bh[s*2+1]);
                    }
                }
            }
        }
    }
}

__device__ __forceinline__ void hmma_store(
    float (&acc)[2][8][4], int M, int row0, float* __restrict__ out, int ldc, int cbase,
    const float* __restrict__ s_bias)
{
    int tid = threadIdx.x, lid = tid & 31, wid = tid >> 5;
    int g = lid >> 2, t = lid & 3;
    int wm = wid & 3, wn = wid >> 2;
    #pragma unroll
    for (int mi = 0; mi < 2; mi++)
        #pragma unroll
        for (int hf = 0; hf < 2; hf++) {
            int r = row0 + wm * 32 + mi * 16 + hf * 8 + g;
            if (r < M) {
                #pragma unroll
                for (int ni = 0; ni < 8; ni++) {
                    int c = wn * 64 + ni * 8 + t * 2;
                    *(float2*)&out[(size_t)r * ldc + cbase + c] = make_float2(
                        acc[mi][ni][hf * 2 + 0] + s_bias[c],
                        acc[mi][ni][hf * 2 + 1] + s_bias[c + 1]);
                }
            }
        }
}

// ---------------- unified GEMM (embeddings) ----------------
__global__ void __launch_bounds__(256, 2) k_gemm_plain(
    const float* __restrict__ A, const float* __restrict__ W, int widx,
    const float* __restrict__ bias, int M, int which)
{
    __shared__ __align__(16) uint32_t smraw[UNION_U32];
    __shared__ float s_bias[DIM];
    int tid = threadIdx.x;
    int row0 = blockIdx.x * 128;
    float* out = which ? g_e : g_h;
    if (tid < DIM) s_bias[tid] = bias[tid];
    __syncthreads();

    if (g_hmma_ok) {
        uint32_t (*hA)[128 * RS2] = reinterpret_cast<uint32_t(*)[128 * RS2]>(smraw);
        uint32_t (*hB)[128 * RS2] = reinterpret_cast<uint32_t(*)[128 * RS2]>(smraw + 2 * 128 * RS2);
        float acc[2][8][4] = {};
        gemm_tile_hmma(A, M, row0, &g_wimg[(size_t)widx * IMG_U32], hA, hB, acc);
        hmma_store(acc, M, row0, out, DIM, 0, s_bias);
    } else {
        float (*As)[16][DIM] = reinterpret_cast<float(*)[16][DIM]>(smraw);
        float (*Bs)[16][DIM] = reinterpret_cast<float(*)[16][DIM]>(smraw + 4096);
        float acc[8][8] = {};
        gemm_mainloop(A, W, M, row0, acc, As, Bs);
        int tx = tid & 15, ty = tid >> 4;
        int c0 = tx * 8;
        #pragma unroll
        for (int i = 0; i < 8; i++) {
            int r = row0 + ty*8 + i;
            if (r < M) {
                #pragma unroll
                for (int j = 0; j < 8; j++)
                    out[(size_t)r * DIM + c0 + j] = acc[i][j] + s_bias[c0 + j];
            }
        }
    }
}

// ---------------- node GEMM: grid (157,2); y=0 -> A,B; y=1 -> D,E ----------------
__global__ void __launch_bounds__(256, 2) k_gemm_node2(
    int l, const float* __restrict__ Aw, const float* __restrict__ Bw,
    const float* __restrict__ Dw, const float* __restrict__ Ew,
    const float* __restrict__ Ab, const float* __restrict__ Bb,
    const float* __restrict__ Db, const float* __restrict__ Eb)
{
    extern __shared__ uint32_t dsm[];
    __shared__ float s_bias[2 * DIM];
    int tid = threadIdx.x;
    int row0 = blockIdx.x * 128;
    int y = blockIdx.y;
    int base = 2 + l * 5;
    int w0 = (y == 0) ? base + 0 : base + 3;
    int w1 = (y == 0) ? base + 1 : base + 4;
    const float* b0 = (y == 0) ? Ab : Db;
    const float* b1 = (y == 0) ? Bb : Eb;
    int cb0 = (y == 0) ? 0 : 2 * DIM;

    if (tid < DIM) { s_bias[tid] = b0[tid]; s_bias[DIM + tid] = b1[tid]; }

    if (g_hmma_ok) {
        hmma_convert_A_full(g_h, N_NODES, row0, dsm);
        {
            float acc[2][8][4] = {};
            hmma_weight_loop(&g_wimg[(size_t)w0 * IMG_U32], dsm, acc);
            hmma_store(acc, N_NODES, row0, g_abde, 512, cb0, &s_bias[0]);
        }
        {
            float acc[2][8][4] = {};
            hmma_weight_loop(&g_wimg[(size_t)w1 * IMG_U32], dsm, acc);
            hmma_store(acc, N_NODES, row0, g_abde, 512, cb0 + DIM, &s_bias[DIM]);
        }
    } else {
        float (*As)[16][DIM] = reinterpret_cast<float(*)[16][DIM]>(dsm);
        float (*Bs)[16][DIM] = reinterpret_cast<float(*)[16][DIM]>(dsm + 4096);
        int tx = tid & 15, ty = tid >> 4;
        int c0 = tx * 8;
        for (int s = 0; s < 2; s++) {
            const float* W = (y == 0) ? (s == 0 ? Aw : Bw) : (s == 0 ? Dw : Ew);
            float acc[8][8] = {};
            __syncthreads();
            gemm_mainloop(g_h, W, N_NODES, row0, acc, As, Bs);
            #pragma unroll
            for (int i = 0; i < 8; i++) {
                int r = row0 + ty*8 + i;
                if (r < N_NODES) {
                    #pragma unroll
                    for (int j = 0; j < 8; j++)
                        g_abde[(size_t)r * 512 + cb0 + s * DIM + c0 + j]
                            = acc[i][j] + s_bias[s * DIM + c0 + j];
                }
            }
            __syncthreads();
        }
    }
}

// ---------------- edge GEMM + gather + (optional) e-BN stats ----------------
__global__ void __launch_bounds__(256, 2) k_gemm_edge(
    int l, const float* __restrict__ Cw, const float* __restrict__ Cb,
    const int* __restrict__ src, const int* __restrict__ dst, int do_estats)
{
    __shared__ __align__(16) uint32_t smraw[UNION_U32];
    __shared__ float s_cb[DIM], s_sum[DIM], s_sq[DIM];
    int tid = threadIdx.x, lid = tid & 31, wid = tid >> 5;
    int row0 = blockIdx.x * 128;
    if (tid < DIM) { s_cb[tid] = Cb[tid]; s_sum[tid] = 0.f; s_sq[tid] = 0.f; }
    __syncthreads();

    if (g_hmma_ok) {
        uint32_t (*hA)[128 * RS2] = reinterpret_cast<uint32_t(*)[128 * RS2]>(smraw);
        uint32_t (*hB)[128 * RS2] = reinterpret_cast<uint32_t(*)[128 * RS2]>(smraw + 2 * 128 * RS2);
        int g = lid >> 2, t = lid & 3;
        int wm = wid & 3, wn = wid >> 2;
        float acc[2][8][4] = {};
        gemm_tile_hmma(g_e, N_EDGES, row0, &g_wimg[(size_t)(2 + l * 5 + 2) * IMG_U32], hA, hB, acc);

        int rows[4], svr[4], dvr[4];
        #pragma unroll
        for (int ridx = 0; ridx < 4; ridx++) {
            int mi = ridx >> 1, hf = ridx & 1;
            rows[ridx] = row0 + wm * 32 + mi * 16 + hf * 8 + g;
            svr[ridx] = src[rows[ridx]];
            dvr[ridx] = dst[rows[ridx]];
        }
        #pragma unroll
        for (int ni = 0; ni < 8; ni++) {
            int c = wn * 64 + ni * 8 + t * 2;
            float cb0 = s_cb[c], cb1 = s_cb[c + 1];
            float s0 = 0.f, s1 = 0.f, q0 = 0.f, q1 = 0.f;
            #pragma unroll
            for (int ridx = 0; ridx < 4; ridx++) {
                int mi = ridx >> 1, hf = ridx & 1;
                float2 dD = *(const float2*)&g_abde[(size_t)svr[ridx] * 512 + 256 + c];
                float2 dE = *(const float2*)&g_abde[(size_t)dvr[ridx] * 512 + 384 + c];
                float v0 = acc[mi][ni][hf * 2 + 0] + cb0 + dD.x + dE.x;
                float v1 = acc[mi][ni][hf * 2 + 1] + cb1 + dD.y + dE.y;
                *(float2*)&g_enew[(size_t)rows[ridx] * DIM + c] = make_float2(v0, v1);
                s0 += v0; q0 += v0 * v0;
                s1 += v1; q1 += v1 * v1;
            }
            if (do_estats) {
                #pragma unroll
                for (int s = 4; s < 32; s <<= 1) {
                    s0 += __shfl_xor_sync(0xffffffffu, s0, s);
                    s1 += __shfl_xor_sync(0xffffffffu, s1, s);
                    q0 += __shfl_xor_sync(0xffffffffu, q0, s);
                    q1 += __shfl_xor_sync(0xffffffffu, q1, s);
                }
                if (g == 0) {
                    atomicAdd(&s_sum[c], s0);     atomicAdd(&s_sq[c], q0);
                    atomicAdd(&s_sum[c + 1], s1); atomicAdd(&s_sq[c + 1], q1);
                }
            }
        }
    } else {
        float (*As)[16][DIM] = reinterpret_cast<float(*)[16][DIM]>(smraw);
        float (*Bs)[16][DIM] = reinterpret_cast<float(*)[16][DIM]>(smraw + 4096);
        float acc[8][8] = {};
        gemm_mainloop(g_e, Cw, N_EDGES, row0, acc, As, Bs);
        __syncthreads();
        int tx = tid & 15, ty = tid >> 4;
        int c0 = tx * 8;
        float cb[8];
        #pragma unroll
        for (int j = 0; j < 8; j++) cb[j] = s_cb[c0 + j];
        float csum[8] = {}, csq[8] = {};
        #pragma unroll 1
        for (int i = 0; i < 8; i++) {
            int r = row0 + ty*8 + i;
            int sv = src[r], dv = dst[r];
            const float* Dp = &g_abde[(size_t)sv * 512 + 256 + c0];
            const float* Ep = &g_abde[(size_t)dv * 512 + 384 + c0];
            float dh[8], eh[8], ev[8];
            *(float4*)(dh)   = *(const float4*)(Dp);
            *(float4*)(dh+4) = *(const float4*)(Dp+4);
            *(float4*)(eh)   = *(const float4*)(Ep);
            *(float4*)(eh+4) = *(const float4*)(Ep+4);
            #pragma unroll
            for (int j = 0; j < 8; j++) {
                float v = acc[i][j] + cb[j] + dh[j] + eh[j];
                ev[j] = v;
                csum[j] += v;
                csq[j]  += v * v;
            }
            *(float4*)&g_enew[(size_t)r * DIM + c0]     = *(float4*)(ev);
            *(float4*)&g_enew[(size_t)r * DIM + c0 + 4] = *(float4*)(ev+4);
        }
        if (do_estats) {
            #pragma unroll
            for (int j = 0; j < 8; j++) {
                atomicAdd(&s_sum[c0 + j], csum[j]);
                atomicAdd(&s_sq[c0 + j],  csq[j]);
            }
        }
    }
    __syncthreads();
    if (do_estats && tid < DIM) {
        atomicAdd(&g_stats[2*DIM + tid], (double)s_sum[tid]);
        atomicAdd(&g_stats[3*DIM + tid], (double)s_sq[tid]);
    }
}

// ================= CSR build =================
__global__ void k_zero_cnt() {
    int i = blockIdx.x * blockDim.x + threadIdx.x;
    if (i < N_NODES) { g_cnt[i] = 0; g_cnt2[i] = 0; }
}
__global__ void k_hist(const int* __restrict__ dst) {
    int e = blockIdx.x * blockDim.x + threadIdx.x;
    if (e < N_EDGES) atomicAdd(&g_cnt[dst[e]], 1);
}
__global__ void k_scan() {
    __shared__ int s[1024];
    int tn = threadIdx.x;
    int base = tn * 20;
    int loc[20];
    int sum = 0;
    #pragma unroll
    for (int j = 0; j < 20; j++) {
        int idx = base + j;
        loc[j] = sum;
        if (idx < N_NODES) sum += g_cnt[idx];
    }
    s[tn] = sum;
    __syncthreads();
    for (int off = 1; off < 1024; off <<= 1) {
        int v = (tn >= off) ? s[tn - off] : 0;
        __syncthreads();
        s[tn] += v;
        __syncthreads();
    }
    int pre = (tn > 0) ? s[tn - 1] : 0;
    #pragma unroll
    for (int j = 0; j < 20; j++) {
        int idx = base + j;
        if (idx < N_NODES) g_csr[idx] = pre + loc[j];
    }
    if (tn == 1023) g_csr[N_NODES] = s[1023];
}
__global__ void k_scatter(const int* __restrict__ src, const int* __restrict__ dst) {
    int e = blockIdx.x * blockDim.x + threadIdx.x;
    if (e < N_EDGES) {
        int d = dst[e];
        int pos = g_csr[d] + atomicAdd(&g_cnt2[d], 1);
        g_perm[pos] = e;
        g_srcp[pos] = src[e];
    }
}
__global__ void k_zero_stats() {
    int i = threadIdx.x;
    if (i < 4 * DIM) g_stats[i] = 0.0;
}

// ---------------- per-node aggregation ----------------
__global__ void __launch_bounds__(128) k_aggregate() {
    int n = blockIdx.x;
    int t = threadIdx.x;
    int beg = g_csr[n], end = g_csr[n + 1];
    float num = 0.f, den = 0.f;
    for (int i = beg; i < end; i++) {
        int e = g_perm[i];
        int s = g_srcp[i];
        float v = g_enew[(size_t)e * DIM + t];
        float bh = g_abde[(size_t)s * 512 + 128 + t];
        float sg = 1.f / (1.f + __expf(-v));
        num = fmaf(sg, bh, num);
        den += sg;
    }
    float hv = g_abde[(size_t)n * 512 + t] + num / (den + 1e-6f);
    g_hnew[n * DIM + t] = hv;
}

__global__ void __launch_bounds__(256) k_hstats() {
    __shared__ float s_sum[DIM];
    __shared__ float s_sq[DIM];
    int tid = threadIdx.x;
    if (tid < DIM) { s_sum[tid] = 0.f; s_sq[tid] = 0.f; }
    __syncthreads();
    int col = tid & 127;
    int rh = tid >> 7;
    int row0 = blockIdx.x * 128;
    float ls = 0.f, lq = 0.f;
    for (int i = rh; i < 128; i += 2) {
        int r = row0 + i;
        if (r < N_NODES) {
            float v = g_hnew[r * DIM + col];
            ls += v; lq += v * v;
        }
    }
    atomicAdd(&s_sum[col], ls);
    atomicAdd(&s_sq[col], lq);
    __syncthreads();
    if (tid < DIM) {
        atomicAdd(&g_stats[tid],       (double)s_sum[tid]);
        atomicAdd(&g_stats[DIM + tid], (double)s_sq[tid]);
    }
}

// e-BN params (stats complete right after edge GEMM); resets e-stats
__global__ void k_finalize_e(const float* __restrict__ ge, const float* __restrict__ be) {
    int t = threadIdx.x;                   // 256 threads
    if (t < DIM) {
        double mu  = g_stats[2*DIM + t] / (double)N_EDGES;
        double var = g_stats[3*DIM + t] / (double)N_EDGES - mu * mu;
        double rstd = 1.0 / sqrt(var + 1e-5);
        float sc = ge[t] * (float)rstd;
        g_bn[2*DIM + t] = sc;
        g_bn[3*DIM + t] = be[t] - (float)mu * sc;
    }
    __syncthreads();
    g_stats[2*DIM + t] = 0.0;              // reset e-stats (256 doubles)
}
// h-BN params (after k_hstats); resets h-stats
__global__ void k_finalize_h(const float* __restrict__ gh, const float* __restrict__ bh) {
    int t = threadIdx.x;                   // 256 threads
    if (t < DIM) {
        double mu  = g_stats[t] / (double)N_NODES;
        double var = g_stats[DIM + t] / (double)N_NODES - mu * mu;
        double rstd = 1.0 / sqrt(var + 1e-5);
        float sc = gh[t] * (float)rstd;
        g_bn[t] = sc;
        g_bn[DIM + t] = bh[t] - (float)mu * sc;
    }
    __syncthreads();
    g_stats[t] = 0.0;                      // reset h-stats (256 doubles)
}

__global__ void k_apply_h() {
    int i4 = blockIdx.x * blockDim.x + threadIdx.x;
    if (i4 < N_NODES * DIM / 4) {
        int c4 = (i4 & 31) * 4;
        float4 v  = *(const float4*)&g_hnew[i4 * 4];
        float4 sc = *(const float4*)&g_bn[c4];
        float4 sh = *(const float4*)&g_bn[DIM + c4];
        float4 hv = *(const float4*)&g_h[i4 * 4];
        hv.x += fmaxf(fmaf(v.x, sc.x, sh.x), 0.f);
        hv.y += fmaxf(fmaf(v.y, sc.y, sh.y), 0.f);
        hv.z += fmaxf(fmaf(v.z, sc.z, sh.z), 0.f);
        hv.w += fmaxf(fmaf(v.w, sc.w, sh.w), 0.f);
        *(float4*)&g_h[i4 * 4] = hv;
    }
}
__global__ void k_apply_e() {
    int i4 = blockIdx.x * blockDim.x + threadIdx.x;
    if (i4 < N_EDGES * DIM / 4) {
        int c4 = (i4 & 31) * 4;
        float4 v  = *(const float4*)&g_enew[(size_t)i4 * 4];
        float4 sc = *(const float4*)&g_bn[2*DIM + c4];
        float4 sh = *(const float4*)&g_bn[3*DIM + c4];
        float4 evv = *(const float4*)&g_e[(size_t)i4 * 4];
        evv.x += fmaxf(fmaf(v.x, sc.x, sh.x), 0.f);
        evv.y += fmaxf(fmaf(v.y, sc.y, sh.y), 0.f);
        evv.z += fmaxf(fmaf(v.z, sc.z, sh.z), 0.f);
        evv.w += fmaxf(fmaf(v.w, sc.w, sh.w), 0.f);
        *(float4*)&g_e[(size_t)i4 * 4] = evv;
    }
}

// ---------------- host launch (multi-stream fork/join, graph-capturable) ----------------
extern "C" void kernel_launch(void* const* d_in, const int* in_sizes, int n_in,
                              void* d_out, int out_size)
{
    const float* h0  = (const float*)d_in[0];
    const float* e0  = (const float*)d_in[1];
    const int*   src = (const int*)  d_in[2];
    const int*   dst = (const int*)  d_in[3];
    const float* Wh  = (const float*)d_in[4];
    const float* bhe = (const float*)d_in[5];
    const float* We  = (const float*)d_in[6];
    const float* bee = (const float*)d_in[7];
    const float* Aw  = (const float*)d_in[8];
    const float* Ab  = (const float*)d_in[9];
    const float* Bw  = (const float*)d_in[10];
    const float* Bb  = (const float*)d_in[11];
    const float* Cw  = (const float*)d_in[12];
    const float* Cb  = (const float*)d_in[13];
    const float* Dw  = (const float*)d_in[14];
    const float* Db  = (const float*)d_in[15];
    const float* Ew  = (const float*)d_in[16];
    const float* Eb  = (const float*)d_in[17];
    const float* gh  = (const float*)d_in[18];
    const float* bh  = (const float*)d_in[19];
    const float* ge  = (const float*)d_in[20];
    const float* be  = (const float*)d_in[21];

    const int grid_node = (N_NODES + 127) / 128;   // 157
    const int grid_edge = N_EDGES / 128;           // 2000

    cudaFuncSetAttribute(k_gemm_node2, cudaFuncAttributeMaxDynamicSharedMemorySize, DYN_BYTES);

    // side stream + events (host objects; kernel_launch runs only twice, no cleanup needed)
    cudaStream_t s2;
    cudaStreamCreateWithFlags(&s2, cudaStreamNonBlocking);
    cudaEvent_t evStart, evCsr, evF[3], evJ[3];
    cudaEventCreateWithFlags(&evStart, cudaEventDisableTiming);
    cudaEventCreateWithFlags(&evCsr,   cudaEventDisableTiming);
    for (int i = 0; i < 3; i++) {
        cudaEventCreateWithFlags(&evF[i], cudaEventDisableTiming);
        cudaEventCreateWithFlags(&evJ[i], cudaEventDisableTiming);
    }

    // fork CSR build onto s2, parallel to weight prep + embeddings
    cudaEventRecord(evStart, 0);
    cudaStreamWaitEvent(s2, evStart, 0);
    k_zero_cnt<<<(N_NODES + 255) / 256, 256, 0, s2>>>();
    k_hist<<<(N_EDGES + 255) / 256, 256, 0, s2>>>(dst);
    k_scan<<<1, 1024, 0, s2>>>();
    k_scatter<<<(N_EDGES + 255) / 256, 256, 0, s2>>>(src, dst);
    cudaEventRecord(evCsr, s2);

    k_probe<<<1, 32>>>();
    k_prep_w<<<22, 256>>>(Wh, We, Aw, Bw, Cw, Dw, Ew);
    k_gemm_plain<<<grid_node, 256>>>(h0, Wh, 0, bhe, N_NODES, 0);
    k_gemm_plain<<<grid_edge, 256>>>(e0, We, 1, bee, N_EDGES, 1);
    k_zero_stats<<<1, 512>>>();

    for (int l = 0; l < 4; l++) {
        int do_e = (l < 3) ? 1 : 0;   // e_3 dead
        k_gemm_node2<<<dim3(grid_node, 2), 256, DYN_BYTES>>>(l,
            Aw + l*DD, Bw + l*DD, Dw + l*DD, Ew + l*DD,
            Ab + l*DIM, Bb + l*DIM, Db + l*DIM, Eb + l*DIM);
        if (l > 0)
            cudaStreamWaitEvent(0, evJ[l - 1], 0);   // g_e update of prev layer done
        k_gemm_edge<<<grid_edge, 256>>>(l, Cw + l*DD, Cb + l*DIM, src, dst, do_e);
        if (do_e) {
            k_finalize_e<<<1, 256>>>(ge + l*DIM, be + l*DIM);
            // fork apply_e onto s2: overlaps aggregate/hstats/apply_h/next node GEMM
            cudaEventRecord(evF[l], 0);
            cudaStreamWaitEvent(s2, evF[l], 0);
            k_apply_e<<<(N_EDGES * DIM / 4 + 255) / 256, 256, 0, s2>>>();
            cudaEventRecord(evJ[l], s2);
        }
        if (l == 0)
            cudaStreamWaitEvent(0, evCsr, 0);        // CSR ready for aggregate
        k_aggregate<<<N_NODES, 128>>>();
        k_hstats<<<grid_node, 256>>>();
        k_finalize_h<<<1, 256>>>(gh + l*DIM, bh + l*DIM);
        k_apply_h<<<(N_NODES * DIM / 4 + 255) / 256, 256>>>();
    }

    cudaMemcpyFromSymbolAsync(d_out, g_h, sizeof(float) * N_NODES * DIM, 0,
                              cudaMemcpyDeviceToDevice, 0);
}

// round 17
// speedup vs baseline: 1.1160x; 1.0686x over previous
#include <cuda_runtime.h>
#include <cuda_fp16.h>
#include <cstdint>

#define N_NODES 20000
#define N_EDGES 256000
#define DIM 128
#define DD (DIM*DIM)

#define RS2 20                       // BK=32 smem row stride (u32)
#define RSA 68                       // full-K A smem row stride (u32)
#define IMG_U32 8192                 // per-matrix fp16 image
#define UNION_U32 8192               // 32KB static smem union (edge/plain kernels)
#define A_SPLIT_OFF (128 * RSA)      // 8704
#define B_BASE      (2 * 128 * RSA)  // 17408
#define DYN_U32   (B_BASE + 128 * RS2)   // 19968
#define DYN_BYTES (DYN_U32 * 4)          // 79872 B (node kernel only)
// edge/plain smem layout (u32 offsets)
#define EA_HI 0
#define EA_LO 2560
#define EB    5120

// ---------------- static device scratch ----------------
__device__ float  g_h   [N_NODES * DIM];
__device__ float  g_e   [N_EDGES * DIM];
__device__ float  g_abde[N_NODES * 4 * DIM];
__device__ float  g_enew[N_EDGES * DIM];
__device__ float  g_hnew[N_NODES * DIM];
__device__ double g_stats[4 * DIM];
__device__ float  g_bn  [4 * DIM];
__device__ int    g_cnt [N_NODES];
__device__ int    g_cnt2[N_NODES];
__device__ int    g_csr [N_NODES + 1];
__device__ int    g_perm[N_EDGES];
__device__ int    g_srcp[N_EDGES];
__device__ uint32_t g_wimg[22 * IMG_U32];
__device__ int    g_hmma_ok;

// ---------------- fp16 helpers ----------------
__device__ __forceinline__ uint32_t pack2h(float a, float b) {
    __half2 h = __floats2half2_rn(a, b);
    return *reinterpret_cast<uint32_t*>(&h);
}
__device__ __forceinline__ void split2h(float a, float b, uint32_t& hi, uint32_t& lo) {
    __half2 h = __floats2half2_rn(a, b);
    float fa = __low2float(h), fb = __high2float(h);
    hi = *reinterpret_cast<uint32_t*>(&h);
    lo = pack2h(a - fa, b - fb);
}
__device__ __forceinline__ void mma16816h(float (&d)[4], const uint32_t (&a)[4],
                                          const uint32_t b0, const uint32_t b1) {
    asm volatile("mma.sync.aligned.m16n8k16.row.col.f32.f16.f16.f32 "
        "{%0,%1,%2,%3}, {%4,%5,%6,%7}, {%8,%9}, {%0,%1,%2,%3};"
        : "+f"(d[0]), "+f"(d[1]), "+f"(d[2]), "+f"(d[3])
        : "r"(a[0]), "r"(a[1]), "r"(a[2]), "r"(a[3]), "r"(b0), "r"(b1));
}
__device__ __forceinline__ void ldsm_x4(uint32_t (&r)[4], uint32_t saddr) {
    asm volatile("ldmatrix.sync.aligned.m8n8.x4.shared.b16 {%0,%1,%2,%3}, [%4];"
        : "=r"(r[0]), "=r"(r[1]), "=r"(r[2]), "=r"(r[3]) : "r"(saddr));
}

// ================= numeric HMMA probe (f16 path) =================
__global__ void k_probe() {
    uint32_t one2 = 0x3c003c00u;   // fp16 {1.0, 1.0}
    uint32_t a[4] = {one2, one2, one2, one2};
    float d[4] = {0.f, 0.f, 0.f, 0.f};
    mma16816h(d, a, one2, one2);   // ones x ones, K=16 -> 16.0
    bool ok = (d[0] == 16.f) && (d[1] == 16.f) && (d[2] == 16.f) && (d[3] == 16.f);
    unsigned m = __ballot_sync(0xffffffffu, ok);
    if ((threadIdx.x & 31) == 0) g_hmma_ok = (m == 0xffffffffu) ? 1 : 0;
}

// ---------------- weight prep: fp32 W[k][n] -> fp16 image (B = W^T, k-contig) ----------------
__global__ void k_prep_w(const float* Wh, const float* We,
                         const float* Aw, const float* Bw, const float* Cw,
                         const float* Dw, const float* Ew)
{
    int bx = blockIdx.x;
    const float* W;
    if (bx == 0) W = Wh;
    else if (bx == 1) W = We;
    else {
        int i = bx - 2, l = i / 5, w = i % 5;
        W = ((w == 0) ? Aw : (w == 1) ? Bw : (w == 2) ? Cw : (w == 3) ? Dw : Ew) + (size_t)l * DD;
    }
    uint32_t* img = &g_wimg[(size_t)bx * IMG_U32];
    for (int p = threadIdx.x; p < 8192; p += blockDim.x) {
        int n = p >> 6, kp = p & 63, k = kp << 1;
        img[n * 64 + kp] = pack2h(W[k * DIM + n], W[(k + 1) * DIM + n]);
    }
}

// ================= SIMT fp32 mainloop (fallback) =================
__device__ __forceinline__ void gemm_mainloop(
    const float* __restrict__ A, const float* __restrict__ B,
    int M, int row0, float (&acc)[8][8],
    float (*As)[16][DIM], float (*Bs)[16][DIM])
{
    const int tid = threadIdx.x;
    const int ty = tid >> 4, tx = tid & 15;
    const int ar0 = tid >> 2, ac0 = (tid & 3) << 2;
    const int ar1 = ar0 + 64;
    const int br0 = tid >> 5, bc0 = (tid & 31) << 2;
    const int br1 = br0 + 8;
    const int r0 = row0 + ar0, r1 = row0 + ar1;
    const float4 z4 = make_float4(0.f, 0.f, 0.f, 0.f);
    float4 av0, av1, bv0, bv1;

    av0 = (r0 < M) ? *(const float4*)&A[(size_t)r0 * DIM + ac0] : z4;
    av1 = (r1 < M) ? *(const float4*)&A[(size_t)r1 * DIM + ac0] : z4;
    bv0 = *(const float4*)&B[br0 * DIM + bc0];
    bv1 = *(const float4*)&B[br1 * DIM + bc0];
    As[0][ac0+0][ar0] = av0.x; As[0][ac0+1][ar0] = av0.y; As[0][ac0+2][ar0] = av0.z; As[0][ac0+3][ar0] = av0.w;
    As[0][ac0+0][ar1] = av1.x; As[0][ac0+1][ar1] = av1.y; As[0][ac0+2][ar1] = av1.z; As[0][ac0+3][ar1] = av1.w;
    *(float4*)&Bs[0][br0][bc0] = bv0;
    *(float4*)&Bs[0][br1][bc0] = bv1;
    __syncthreads();

    av0 = (r0 < M) ? *(const float4*)&A[(size_t)r0 * DIM + 16 + ac0] : z4;
    av1 = (r1 < M) ? *(const float4*)&A[(size_t)r1 * DIM + 16 + ac0] : z4;
    bv0 = *(const float4*)&B[(16 + br0) * DIM + bc0];
    bv1 = *(const float4*)&B[(16 + br1) * DIM + bc0];

    #pragma unroll 1
    for (int it = 0; it < 8; it++) {
        const int cur = it & 1;
        #pragma unroll
        for (int k = 0; k < 16; k++) {
            float a[8], b[8];
            *(float4*)(a)   = *(const float4*)&As[cur][k][ty*8];
            *(float4*)(a+4) = *(const float4*)&As[cur][k][ty*8+4];
            *(float4*)(b)   = *(const float4*)&Bs[cur][k][tx*8];
            *(float4*)(b+4) = *(const float4*)&Bs[cur][k][tx*8+4];
            #pragma unroll
            for (int i = 0; i < 8; i++)
                #pragma unroll
                for (int j = 0; j < 8; j++)
                    acc[i][j] = fmaf(a[i], b[j], acc[i][j]);
        }
        if (it < 7) {
            const int nxt = cur ^ 1;
            As[nxt][ac0+0][ar0] = av0.x; As[nxt][ac0+1][ar0] = av0.y; As[nxt][ac0+2][ar0] = av0.z; As[nxt][ac0+3][ar0] = av0.w;
            As[nxt][ac0+0][ar1] = av1.x; As[nxt][ac0+1][ar1] = av1.y; As[nxt][ac0+2][ar1] = av1.z; As[nxt][ac0+3][ar1] = av1.w;
            *(float4*)&Bs[nxt][br0][bc0] = bv0;
            *(float4*)&Bs[nxt][br1][bc0] = bv1;
            __syncthreads();
            if (it < 6) {
                int kk = (it + 2) * 16;
                av0 = (r0 < M) ? *(const float4*)&A[(size_t)r0 * DIM + kk + ac0] : z4;
                av1 = (r1 < M) ? *(const float4*)&A[(size_t)r1 * DIM + kk + ac0] : z4;
                bv0 = *(const float4*)&B[(kk + br0) * DIM + bc0];
                bv1 = *(const float4*)&B[(kk + br1) * DIM + bc0];
            }
        }
    }
}

// ================= HMMA fp16 BK=32 tile (edge/plain kernels) =================
__device__ __forceinline__ void gemm_tile_hmma(
    const float* __restrict__ Asrc, int M, int row0, const uint32_t* __restrict__ wimg,
    uint32_t* sm, float (&acc)[2][8][4])
{
    int tid = threadIdx.x, lid = tid & 31, wid = tid >> 5;
    int wm = wid & 3, wn = wid >> 2;
    int lrow = lid & 7, lj = lid >> 3;
    int a_row_off = ((lj & 1) << 3) + lrow;
    int a_word    = (lj >> 1) << 2;
    int b_row_off = ((lj >> 1) << 3) + lrow;
    int b_word    = (lj & 1) << 2;
    uint32_t sA0 = (uint32_t)__cvta_generic_to_shared(sm + EA_HI);
    uint32_t sA1 = (uint32_t)__cvta_generic_to_shared(sm + EA_LO);
    uint32_t sB  = (uint32_t)__cvta_generic_to_shared(sm + EB);

    #pragma unroll 1
    for (int it = 0; it < 4; it++) {
        if (it) __syncthreads();
        #pragma unroll
        for (int q = 0; q < 8; q++) {
            int p = tid + q * 256;
            int row = p >> 4, kpl = p & 15;
            int r = row0 + row;
            float2 v = (r < M) ? *(const float2*)&Asrc[(size_t)r * DIM + it * 32 + kpl * 2]
                               : make_float2(0.f, 0.f);
            uint32_t hi, lo;
            split2h(v.x, v.y, hi, lo);
            sm[EA_HI + row * RS2 + kpl] = hi;
            sm[EA_LO + row * RS2 + kpl] = lo;
        }
        #pragma unroll
        for (int q = 0; q < 8; q++) {
            int p = tid + q * 256;
            int n = p >> 4, kpl = p & 15;
            sm[EB + n * RS2 + kpl] = wimg[n * 64 + it * 16 + kpl];
        }
        __syncthreads();
        #pragma unroll
        for (int kk = 0; kk < 2; kk++) {
            uint32_t ah[2][4], al[2][4];
            #pragma unroll
            for (int mi = 0; mi < 2; mi++) {
                uint32_t off = (uint32_t)(((wm * 32 + mi * 16 + a_row_off) * RS2
                                           + kk * 8 + a_word) * 4);
                ldsm_x4(ah[mi], sA0 + off);
                ldsm_x4(al[mi], sA1 + off);
            }
            #pragma unroll
            for (int np = 0; np < 4; np++) {
                uint32_t off = (uint32_t)(((wn * 64 + np * 16 + b_row_off) * RS2
                                           + kk * 8 + b_word) * 4);
                uint32_t bh[4];
                ldsm_x4(bh, sB + off);
                #pragma unroll
                for (int s = 0; s < 2; s++) {
                    int ni = np * 2 + s;
                    #pragma unroll
                    for (int mi = 0; mi < 2; mi++) {
                        mma16816h(acc[mi][ni], ah[mi], bh[s*2], bh[s*2+1]);
                        mma16816h(acc[mi][ni], al[mi], bh[s*2], bh[s*2+1]);
                    }
                }
            }
        }
    }
}

// ================= full-K A pieces (node kernel) =================
__device__ __forceinline__ void hmma_convert_A_full(
    const float* __restrict__ Asrc, int M, int row0, uint32_t* dsm)
{
    int tid = threadIdx.x;
    #pragma unroll
    for (int q = 0; q < 32; q++) {
        int p = tid + q * 256;
        int row = p >> 6, kw = p & 63;
        int r = row0 + row;
        float2 v = (r < M) ? *(const float2*)&Asrc[(size_t)r * DIM + kw * 2]
                           : make_float2(0.f, 0.f);
        uint32_t hi, lo;
        split2h(v.x, v.y, hi, lo);
        dsm[row * RSA + kw] = hi;
        dsm[A_SPLIT_OFF + row * RSA + kw] = lo;
    }
}
__device__ __forceinline__ void hmma_weight_loop(
    const uint32_t* __restrict__ wimg, uint32_t* dsm, float (&acc)[2][8][4])
{
    int tid = threadIdx.x, lid = tid & 31, wid = tid >> 5;
    int wm = wid & 3, wn = wid >> 2;
    int lrow = lid & 7, lj = lid >> 3;
    int a_row_off = ((lj & 1) << 3) + lrow;
    int a_word    = (lj >> 1) << 2;
    int b_row_off = ((lj >> 1) << 3) + lrow;
    int b_word    = (lj & 1) << 2;
    uint32_t sA0 = (uint32_t)__cvta_generic_to_shared(dsm);
    uint32_t sA1 = (uint32_t)__cvta_generic_to_shared(dsm + A_SPLIT_OFF);
    uint32_t sB  = (uint32_t)__cvta_generic_to_shared(dsm + B_BASE);

    #pragma unroll 1
    for (int it = 0; it < 4; it++) {
        __syncthreads();
        #pragma unroll
        for (int q = 0; q < 8; q++) {
            int p = tid + q * 256;
            int n = p >> 4, kpl = p & 15;
            dsm[B_BASE + n * RS2 + kpl] = wimg[n * 64 + it * 16 + kpl];
        }
        __syncthreads();
        #pragma unroll
        for (int kk = 0; kk < 2; kk++) {
            uint32_t ah[2][4], al[2][4];
            #pragma unroll
            for (int mi = 0; mi < 2; mi++) {
                uint32_t off = (uint32_t)(((wm * 32 + mi * 16 + a_row_off) * RSA
                                           + it * 16 + kk * 8 + a_word) * 4);
                ldsm_x4(ah[mi], sA0 + off);
                ldsm_x4(al[mi], sA1 + off);
            }
            #pragma unroll
            for (int np = 0; np < 4; np++) {
                uint32_t off = (uint32_t)(((wn * 64 + np * 16 + b_row_off) * RS2
                                           + kk * 8 + b_word) * 4);
                uint32_t bh[4];
                ldsm_x4(bh, sB + off);
                #pragma unroll
                for (int s = 0; s < 2; s++) {
                    int ni = np * 2 + s;
                    #pragma unroll
                    for (int mi = 0; mi < 2; mi++) {
                        mma16816h(acc[mi][ni], ah[mi], bh[s*2], bh[s*2+1]);
                        mma16816h(acc[mi][ni], al[mi], bh[s*2], bh[s*2+1]);
                    }
                }
            }
        }
    }
}

__device__ __forceinline__ void hmma_store(
    float (&acc)[2][8][4], int M, int row0, float* __restrict__ out, int ldc, int cbase,
    const float* __restrict__ s_bias)
{
    int tid = threadIdx.x, lid = tid & 31, wid = tid >> 5;
    int g = lid >> 2, t = lid & 3;
    int wm = wid & 3, wn = wid >> 2;
    #pragma unroll
    for (int mi = 0; mi < 2; mi++)
        #pragma unroll
        for (int hf = 0; hf < 2; hf++) {
            int r = row0 + wm * 32 + mi * 16 + hf * 8 + g;
            if (r < M) {
                #pragma unroll
                for (int ni = 0; ni < 8; ni++) {
                    int c = wn * 64 + ni * 8 + t * 2;
                    *(float2*)&out[(size_t)r * ldc + cbase + c] = make_float2(
                        acc[mi][ni][hf * 2 + 0] + s_bias[c],
                        acc[mi][ni][hf * 2 + 1] + s_bias[c + 1]);
                }
            }
        }
}

// ---------------- unified GEMM (embeddings) ----------------
__global__ void __launch_bounds__(256, 2) k_gemm_plain(
    const float* __restrict__ A, const float* __restrict__ W, int widx,
    const float* __restrict__ bias, int M, int which)
{
    __shared__ __align__(16) uint32_t smraw[UNION_U32];
    __shared__ float s_bias[DIM];
    int tid = threadIdx.x;
    int row0 = blockIdx.x * 128;
    float* out = which ? g_e : g_h;
    if (tid < DIM) s_bias[tid] = bias[tid];
    __syncthreads();

    if (g_hmma_ok) {
        float acc[2][8][4] = {};
        gemm_tile_hmma(A, M, row0, &g_wimg[(size_t)widx * IMG_U32], smraw, acc);
        hmma_store(acc, M, row0, out, DIM, 0, s_bias);
    } else {
        float (*As)[16][DIM] = reinterpret_cast<float(*)[16][DIM]>(smraw);
        float (*Bs)[16][DIM] = reinterpret_cast<float(*)[16][DIM]>(smraw + 4096);
        float acc[8][8] = {};
        gemm_mainloop(A, W, M, row0, acc, As, Bs);
        int tx = tid & 15, ty = tid >> 4;
        int c0 = tx * 8;
        #pragma unroll
        for (int i = 0; i < 8; i++) {
            int r = row0 + ty*8 + i;
            if (r < M) {
                #pragma unroll
                for (int j = 0; j < 8; j++)
                    out[(size_t)r * DIM + c0 + j] = acc[i][j] + s_bias[c0 + j];
            }
        }
    }
}

// ---------------- node GEMM: grid (157,2); y=0 -> A,B; y=1 -> D,E ----------------
__global__ void __launch_bounds__(256, 2) k_gemm_node2(
    int l, const float* __restrict__ Aw, const float* __restrict__ Bw,
    const float* __restrict__ Dw, const float* __restrict__ Ew,
    const float* __restrict__ Ab, const float* __restrict__ Bb,
    const float* __restrict__ Db, const float* __restrict__ Eb)
{
    extern __shared__ uint32_t dsm[];
    __shared__ float s_bias[2 * DIM];
    int tid = threadIdx.x;
    int row0 = blockIdx.x * 128;
    int y = blockIdx.y;
    int base = 2 + l * 5;
    int w0 = (y == 0) ? base + 0 : base + 3;
    int w1 = (y == 0) ? base + 1 : base + 4;
    const float* b0 = (y == 0) ? Ab : Db;
    const float* b1 = (y == 0) ? Bb : Eb;
    int cb0 = (y == 0) ? 0 : 2 * DIM;

    if (tid < DIM) { s_bias[tid] = b0[tid]; s_bias[DIM + tid] = b1[tid]; }

    if (g_hmma_ok) {
        hmma_convert_A_full(g_h, N_NODES, row0, dsm);
        {
            float acc[2][8][4] = {};
            hmma_weight_loop(&g_wimg[(size_t)w0 * IMG_U32], dsm, acc);
            hmma_store(acc, N_NODES, row0, g_abde, 512, cb0, &s_bias[0]);
        }
        {
            float acc[2][8][4] = {};
            hmma_weight_loop(&g_wimg[(size_t)w1 * IMG_U32], dsm, acc);
            hmma_store(acc, N_NODES, row0, g_abde, 512, cb0 + DIM, &s_bias[DIM]);
        }
    } else {
        float (*As)[16][DIM] = reinterpret_cast<float(*)[16][DIM]>(dsm);
        float (*Bs)[16][DIM] = reinterpret_cast<float(*)[16][DIM]>(dsm + 4096);
        int tx = tid & 15, ty = tid >> 4;
        int c0 = tx * 8;
        for (int s = 0; s < 2; s++) {
            const float* W = (y == 0) ? (s == 0 ? Aw : Bw) : (s == 0 ? Dw : Ew);
            float acc[8][8] = {};
            __syncthreads();
            gemm_mainloop(g_h, W, N_NODES, row0, acc, As, Bs);
            #pragma unroll
            for (int i = 0; i < 8; i++) {
                int r = row0 + ty*8 + i;
                if (r < N_NODES) {
                    #pragma unroll
                    for (int j = 0; j < 8; j++)
                        g_abde[(size_t)r * 512 + cb0 + s * DIM + c0 + j]
                            = acc[i][j] + s_bias[s * DIM + c0 + j];
                }
            }
            __syncthreads();
        }
    }
}

// ---------------- edge GEMM + gather + (optional) e-BN stats ----------------
__global__ void __launch_bounds__(256, 2) k_gemm_edge(
    int l, const float* __restrict__ Cw, const float* __restrict__ Cb,
    const int* __restrict__ src, const int* __restrict__ dst, int do_estats)
{
    __shared__ __align__(16) uint32_t smraw[UNION_U32];
    __shared__ float s_cb[DIM], s_sum[DIM], s_sq[DIM];
    int tid = threadIdx.x, lid = tid & 31, wid = tid >> 5;
    int row0 = blockIdx.x * 128;
    if (tid < DIM) { s_cb[tid] = Cb[tid]; s_sum[tid] = 0.f; s_sq[tid] = 0.f; }
    __syncthreads();

    if (g_hmma_ok) {
        int g = lid >> 2, t = lid & 3;
        int wm = wid & 3, wn = wid >> 2;
        float acc[2][8][4] = {};
        gemm_tile_hmma(g_e, N_EDGES, row0, &g_wimg[(size_t)(2 + l * 5 + 2) * IMG_U32], smraw, acc);

        int rows[4], svr[4], dvr[4];
        #pragma unroll
        for (int ridx = 0; ridx < 4; ridx++) {
            int mi = ridx >> 1, hf = ridx & 1;
            rows[ridx] = row0 + wm * 32 + mi * 16 + hf * 8 + g;
            svr[ridx] = src[rows[ridx]];
            dvr[ridx] = dst[rows[ridx]];
        }
        #pragma unroll
        for (int ni = 0; ni < 8; ni++) {
            int c = wn * 64 + ni * 8 + t * 2;
            float cb0 = s_cb[c], cb1 = s_cb[c + 1];
            float s0 = 0.f, s1 = 0.f, q0 = 0.f, q1 = 0.f;
            #pragma unroll
            for (int ridx = 0; ridx < 4; ridx++) {
                int mi = ridx >> 1, hf = ridx & 1;
                float2 dD = *(const float2*)&g_abde[(size_t)svr[ridx] * 512 + 256 + c];
                float2 dE = *(const float2*)&g_abde[(size_t)dvr[ridx] * 512 + 384 + c];
                float v0 = acc[mi][ni][hf * 2 + 0] + cb0 + dD.x + dE.x;
                float v1 = acc[mi][ni][hf * 2 + 1] + cb1 + dD.y + dE.y;
                *(float2*)&g_enew[(size_t)rows[ridx] * DIM + c] = make_float2(v0, v1);
                s0 += v0; q0 += v0 * v0;
                s1 += v1; q1 += v1 * v1;
            }
            if (do_estats) {
                #pragma unroll
                for (int s = 4; s < 32; s <<= 1) {
                    s0 += __shfl_xor_sync(0xffffffffu, s0, s);
                    s1 += __shfl_xor_sync(0xffffffffu, s1, s);
                    q0 += __shfl_xor_sync(0xffffffffu, q0, s);
                    q1 += __shfl_xor_sync(0xffffffffu, q1, s);
                }
                if (g == 0) {
                    atomicAdd(&s_sum[c], s0);     atomicAdd(&s_sq[c], q0);
                    atomicAdd(&s_sum[c + 1], s1); atomicAdd(&s_sq[c + 1], q1);
                }
            }
        }
    } else {
        float (*As)[16][DIM] = reinterpret_cast<float(*)[16][DIM]>(smraw);
        float (*Bs)[16][DIM] = reinterpret_cast<float(*)[16][DIM]>(smraw + 4096);
        float acc[8][8] = {};
        gemm_mainloop(g_e, Cw, N_EDGES, row0, acc, As, Bs);
        __syncthreads();
        int tx = tid & 15, ty = tid >> 4;
        int c0 = tx * 8;
        float cb[8];
        #pragma unroll
        for (int j = 0; j < 8; j++) cb[j] = s_cb[c0 + j];
        float csum[8] = {}, csq[8] = {};
        #pragma unroll 1
        for (int i = 0; i < 8; i++) {
            int r = row0 + ty*8 + i;
            int sv = src[r], dv = dst[r];
            const float* Dp = &g_abde[(size_t)sv * 512 + 256 + c0];
            const float* Ep = &g_abde[(size_t)dv * 512 + 384 + c0];
            float dh[8], eh[8], ev[8];
            *(float4*)(dh)   = *(const float4*)(Dp);
            *(float4*)(dh+4) = *(const float4*)(Dp+4);
            *(float4*)(eh)   = *(const float4*)(Ep);
            *(float4*)(eh+4) = *(const float4*)(Ep+4);
            #pragma unroll
            for (int j = 0; j < 8; j++) {
                float v = acc[i][j] + cb[j] + dh[j] + eh[j];
                ev[j] = v;
                csum[j] += v;
                csq[j]  += v * v;
            }
            *(float4*)&g_enew[(size_t)r * DIM + c0]     = *(float4*)(ev);
            *(float4*)&g_enew[(size_t)r * DIM + c0 + 4] = *(float4*)(ev+4);
        }
        if (do_estats) {
            #pragma unroll
            for (int j = 0; j < 8; j++) {
                atomicAdd(&s_sum[c0 + j], csum[j]);
                atomicAdd(&s_sq[c0 + j],  csq[j]);
            }
        }
    }
    __syncthreads();
    if (do_estats && tid < DIM) {
        atomicAdd(&g_stats[2*DIM + tid], (double)s_sum[tid]);
        atomicAdd(&g_stats[3*DIM + tid], (double)s_sq[tid]);
    }
}

// ================= CSR build =================
__global__ void k_zero_cnt() {
    int i = blockIdx.x * blockDim.x + threadIdx.x;
    if (i < N_NODES) { g_cnt[i] = 0; g_cnt2[i] = 0; }
}
__global__ void k_hist(const int* __restrict__ dst) {
    int e = blockIdx.x * blockDim.x + threadIdx.x;
    if (e < N_EDGES) atomicAdd(&g_cnt[dst[e]], 1);
}
__global__ void k_scan() {
    __shared__ int s[1024];
    int tn = threadIdx.x;
    int base = tn * 20;
    int loc[20];
    int sum = 0;
    #pragma unroll
    for (int j = 0; j < 20; j++) {
        int idx = base + j;
        loc[j] = sum;
        if (idx < N_NODES) sum += g_cnt[idx];
    }
    s[tn] = sum;
    __syncthreads();
    for (int off = 1; off < 1024; off <<= 1) {
        int v = (tn >= off) ? s[tn - off] : 0;
        __syncthreads();
        s[tn] += v;
        __syncthreads();
    }
    int pre = (tn > 0) ? s[tn - 1] : 0;
    #pragma unroll
    for (int j = 0; j < 20; j++) {
        int idx = base + j;
        if (idx < N_NODES) g_csr[idx] = pre + loc[j];
    }
    if (tn == 1023) g_csr[N_NODES] = s[1023];
}
__global__ void k_scatter(const int* __restrict__ src, const int* __restrict__ dst) {
    int e = blockIdx.x * blockDim.x + threadIdx.x;
    if (e < N_EDGES) {
        int d = dst[e];
        int pos = g_csr[d] + atomicAdd(&g_cnt2[d], 1);
        g_perm[pos] = e;
        g_srcp[pos] = src[e];
    }
}
__global__ void k_zero_stats() {
    int i = threadIdx.x;
    if (i < 4 * DIM) g_stats[i] = 0.0;
}

// ---------------- per-node aggregation ----------------
__global__ void __launch_bounds__(128) k_aggregate() {
    int n = blockIdx.x;
    int t = threadIdx.x;
    int beg = g_csr[n], end = g_csr[n + 1];
    float num = 0.f, den = 0.f;
    for (int i = beg; i < end; i++) {
        int e = g_perm[i];
        int s = g_srcp[i];
        float v = g_enew[(size_t)e * DIM + t];
        float bh = g_abde[(size_t)s * 512 + 128 + t];
        float sg = 1.f / (1.f + __expf(-v));
        num = fmaf(sg, bh, num);
        den += sg;
    }
    float hv = g_abde[(size_t)n * 512 + t] + num / (den + 1e-6f);
    g_hnew[n * DIM + t] = hv;
}

__global__ void __launch_bounds__(256) k_hstats() {
    __shared__ float s_sum[DIM];
    __shared__ float s_sq[DIM];
    int tid = threadIdx.x;
    if (tid < DIM) { s_sum[tid] = 0.f; s_sq[tid] = 0.f; }
    __syncthreads();
    int col = tid & 127;
    int rh = tid >> 7;
    int row0 = blockIdx.x * 128;
    float ls = 0.f, lq = 0.f;
    for (int i = rh; i < 128; i += 2) {
        int r = row0 + i;
        if (r < N_NODES) {
            float v = g_hnew[r * DIM + col];
            ls += v; lq += v * v;
        }
    }
    atomicAdd(&s_sum[col], ls);
    atomicAdd(&s_sq[col], lq);
    __syncthreads();
    if (tid < DIM) {
        atomicAdd(&g_stats[tid],       (double)s_sum[tid]);
        atomicAdd(&g_stats[DIM + tid], (double)s_sq[tid]);
    }
}

// e-BN params; resets e-stats
__global__ void k_finalize_e(const float* __restrict__ ge, const float* __restrict__ be) {
    int t = threadIdx.x;
    if (t < DIM) {
        double mu  = g_stats[2*DIM + t] / (double)N_EDGES;
        double var = g_stats[3*DIM + t] / (double)N_EDGES - mu * mu;
        double rstd = 1.0 / sqrt(var + 1e-5);
        float sc = ge[t] * (float)rstd;
        g_bn[2*DIM + t] = sc;
        g_bn[3*DIM + t] = be[t] - (float)mu * sc;
    }
    __syncthreads();
    g_stats[2*DIM + t] = 0.0;
}
// h-BN params; resets h-stats
__global__ void k_finalize_h(const float* __restrict__ gh, const float* __restrict__ bh) {
    int t = threadIdx.x;
    if (t < DIM) {
        double mu  = g_stats[t] / (double)N_NODES;
        double var = g_stats[DIM + t] / (double)N_NODES - mu * mu;
        double rstd = 1.0 / sqrt(var + 1e-5);
        float sc = gh[t] * (float)rstd;
        g_bn[t] = sc;
        g_bn[DIM + t] = bh[t] - (float)mu * sc;
    }
    __syncthreads();
    g_stats[t] = 0.0;
}

__global__ void k_apply_h() {
    int i4 = blockIdx.x * blockDim.x + threadIdx.x;
    if (i4 < N_NODES * DIM / 4) {
        int c4 = (i4 & 31) * 4;
        float4 v  = *(const float4*)&g_hnew[i4 * 4];
        float4 sc = *(const float4*)&g_bn[c4];
        float4 sh = *(const float4*)&g_bn[DIM + c4];
        float4 hv = *(const float4*)&g_h[i4 * 4];
        hv.x += fmaxf(fmaf(v.x, sc.x, sh.x), 0.f);
        hv.y += fmaxf(fmaf(v.y, sc.y, sh.y), 0.f);
        hv.z += fmaxf(fmaf(v.z, sc.z, sh.z), 0.f);
        hv.w += fmaxf(fmaf(v.w, sc.w, sh.w), 0.f);
        *(float4*)&g_h[i4 * 4] = hv;
    }
}
__global__ void k_apply_e() {
    int i4 = blockIdx.x * blockDim.x + threadIdx.x;
    if (i4 < N_EDGES * DIM / 4) {
        int c4 = (i4 & 31) * 4;
        float4 v  = *(const float4*)&g_enew[(size_t)i4 * 4];
        float4 sc = *(const float4*)&g_bn[2*DIM + c4];
        float4 sh = *(const float4*)&g_bn[3*DIM + c4];
        float4 evv = *(const float4*)&g_e[(size_t)i4 * 4];
        evv.x += fmaxf(fmaf(v.x, sc.x, sh.x), 0.f);
        evv.y += fmaxf(fmaf(v.y, sc.y, sh.y), 0.f);
        evv.z += fmaxf(fmaf(v.z, sc.z, sh.z), 0.f);
        evv.w += fmaxf(fmaf(v.w, sc.w, sh.w), 0.f);
        *(float4*)&g_e[(size_t)i4 * 4] = evv;
    }
}

// ---------------- host launch (multi-stream fork/join, graph-capturable) ----------------
extern "C" void kernel_launch(void* const* d_in, const int* in_sizes, int n_in,
                              void* d_out, int out_size)
{
    const float* h0  = (const float*)d_in[0];
    const float* e0  = (const float*)d_in[1];
    const int*   src = (const int*)  d_in[2];
    const int*   dst = (const int*)  d_in[3];
    const float* Wh  = (const float*)d_in[4];
    const float* bhe = (const float*)d_in[5];
    const float* We  = (const float*)d_in[6];
    const float* bee = (const float*)d_in[7];
    const float* Aw  = (const float*)d_in[8];
    const float* Ab  = (const float*)d_in[9];
    const float* Bw  = (const float*)d_in[10];
    const float* Bb  = (const float*)d_in[11];
    const float* Cw  = (const float*)d_in[12];
    const float* Cb  = (const float*)d_in[13];
    const float* Dw  = (const float*)d_in[14];
    const float* Db  = (const float*)d_in[15];
    const float* Ew  = (const float*)d_in[16];
    const float* Eb  = (const float*)d_in[17];
    const float* gh  = (const float*)d_in[18];
    const float* bh  = (const float*)d_in[19];
    const float* ge  = (const float*)d_in[20];
    const float* be  = (const float*)d_in[21];

    const int grid_node = (N_NODES + 127) / 128;   // 157
    const int grid_edge = N_EDGES / 128;           // 2000

    cudaFuncSetAttribute(k_gemm_node2, cudaFuncAttributeMaxDynamicSharedMemorySize, DYN_BYTES);

    cudaStream_t s2;
    cudaStreamCreateWithFlags(&s2, cudaStreamNonBlocking);
    cudaEvent_t evStart, evCsr, evF[3], evJ[3];
    cudaEventCreateWithFlags(&evStart, cudaEventDisableTiming);
    cudaEventCreateWithFlags(&evCsr,   cudaEventDisableTiming);
    for (int i = 0; i < 3; i++) {
        cudaEventCreateWithFlags(&evF[i], cudaEventDisableTiming);
        cudaEventCreateWithFlags(&evJ[i], cudaEventDisableTiming);
    }

    // fork CSR build onto s2, parallel to weight prep + embeddings
    cudaEventRecord(evStart, 0);
    cudaStreamWaitEvent(s2, evStart, 0);
    k_zero_cnt<<<(N_NODES + 255) / 256, 256, 0, s2>>>();
    k_hist<<<(N_EDGES + 255) / 256, 256, 0, s2>>>(dst);
    k_scan<<<1, 1024, 0, s2>>>();
    k_scatter<<<(N_EDGES + 255) / 256, 256, 0, s2>>>(src, dst);
    cudaEventRecord(evCsr, s2);

    k_probe<<<1, 32>>>();
    k_prep_w<<<22, 256>>>(Wh, We, Aw, Bw, Cw, Dw, Ew);
    k_gemm_plain<<<grid_node, 256>>>(h0, Wh, 0, bhe, N_NODES, 0);
    k_gemm_plain<<<grid_edge, 256>>>(e0, We, 1, bee, N_EDGES, 1);
    k_zero_stats<<<1, 512>>>();

    for (int l = 0; l < 4; l++) {
        int do_e = (l < 3) ? 1 : 0;   // e_3 dead
        k_gemm_node2<<<dim3(grid_node, 2), 256, DYN_BYTES>>>(l,
            Aw + l*DD, Bw + l*DD, Dw + l*DD, Ew + l*DD,
            Ab + l*DIM, Bb + l*DIM, Db + l*DIM, Eb + l*DIM);
        if (l > 0)
            cudaStreamWaitEvent(0, evJ[l - 1], 0);
        k_gemm_edge<<<grid_edge, 256>>>(l, Cw + l*DD, Cb + l*DIM, src, dst, do_e);
        if (do_e) {
            k_finalize_e<<<1, 256>>>(ge + l*DIM, be + l*DIM);
            cudaEventRecord(evF[l], 0);
            cudaStreamWaitEvent(s2, evF[l], 0);
            k_apply_e<<<(N_EDGES * DIM / 4 + 255) / 256, 256, 0, s2>>>();
            cudaEventRecord(evJ[l], s2);
        }
        if (l == 0)
            cudaStreamWaitEvent(0, evCsr, 0);
        k_aggregate<<<N_NODES, 128>>>();
        k_hstats<<<grid_node, 256>>>();
        k_finalize_h<<<1, 256>>>(gh + l*DIM, bh + l*DIM);
        k_apply_h<<<(N_NODES * DIM / 4 + 255) / 256, 256>>>();
    }

    cudaMemcpyFromSymbolAsync(d_out, g_h, sizeof(float) * N_NODES * DIM, 0,
                              cudaMemcpyDeviceToDevice, 0);
}